// round 8
// baseline (speedup 1.0000x reference)
#include <cuda_runtime.h>
#include <cuda_fp16.h>
#include <cstdint>

// ---------------------------------------------------------------------------
// ProductionFastMQA round 8: single-sync ring pipelines.
//   * GEMM: 3-stage smem ring, prefetch depth 2, ONE __syncthreads/iter
//   * flash: K and V both double-buffered, ONE __syncthreads/iter, no
//     mid-loop barrier; V prefetched a full iteration ahead
//   * arithmetic identical to round 7 (fp16x2)
// ---------------------------------------------------------------------------

#define HIDDEN   2048
#define HEADS    16
#define HEAD_DIM 128
#define BB       2
#define SS       2048
#define SCALE    0.08838834764831845f
#define LOG2E    1.4426950408889634f
#define QSCALE   (SCALE * LOG2E)
#define NQKV     2304
#define KVLD     256

// gemm tiles
#define BM   128
#define BN   128
#define BKb  32
#define ASTR (BKb + 8)            // 40 halves
#define ASZ  (BM * ASTR)          // 5120 halves
#define GSTAGE (3 * ASZ * 2)      // Ah,Al,B per stage = 30720 B
#define SMEM_NK (3 * GSTAGE)      // 92160 B (3-stage ring)

// flash tiles
#define TQ 128
#define TK 128
#define DD 128
#define FSTR 136
#define FTB  (TQ * FSTR * 2)      // 34816 B
#define FSMEM (4 * FTB)           // K0 K1 V0 V1 = 139264 B

// ----------------------------- scratch -------------------------------------
__device__ __half g_xh[BB*SS*HIDDEN],  g_xl[BB*SS*HIDDEN];
__device__ __half g_w[NQKV*HIDDEN];
__device__ __half g_ow[HIDDEN*HIDDEN];
__device__ __half g_qh[BB*SS*HIDDEN],  g_ql[BB*SS*HIDDEN];
__device__ __half g_kv[BB*SS*KVLD];
__device__ __half g_ath[BB*SS*HIDDEN], g_atl[BB*SS*HIDDEN];

// ----------------------------- PTX helpers ---------------------------------
__device__ __forceinline__ uint32_t smem_u32(const void* p) {
    uint32_t a;
    asm("{ .reg .u64 t; cvta.to.shared.u64 t, %1; cvt.u32.u64 %0, t; }"
        : "=r"(a) : "l"(p));
    return a;
}
__device__ __forceinline__ void ldm4(uint32_t* r, uint32_t a) {
    asm volatile("ldmatrix.sync.aligned.m8n8.x4.shared.b16 {%0,%1,%2,%3},[%4];"
                 : "=r"(r[0]), "=r"(r[1]), "=r"(r[2]), "=r"(r[3]) : "r"(a));
}
__device__ __forceinline__ void ldm4t(uint32_t* r, uint32_t a) {
    asm volatile("ldmatrix.sync.aligned.m8n8.x4.trans.shared.b16 {%0,%1,%2,%3},[%4];"
                 : "=r"(r[0]), "=r"(r[1]), "=r"(r[2]), "=r"(r[3]) : "r"(a));
}
__device__ __forceinline__ void cpa16(uint32_t d, const void* s) {
    asm volatile("cp.async.cg.shared.global [%0],[%1],16;" :: "r"(d), "l"(s));
}
__device__ __forceinline__ void mma16(float* c, const uint32_t* a, const uint32_t* b) {
    asm volatile(
        "mma.sync.aligned.m16n8k16.row.col.f32.f16.f16.f32 "
        "{%0,%1,%2,%3},{%4,%5,%6,%7},{%8,%9},{%0,%1,%2,%3};"
        : "+f"(c[0]), "+f"(c[1]), "+f"(c[2]), "+f"(c[3])
        : "r"(a[0]), "r"(a[1]), "r"(a[2]), "r"(a[3]), "r"(b[0]), "r"(b[1]));
}
__device__ __forceinline__ void packpair(float a, float b, uint32_t& hi, uint32_t& lo) {
    __half2 H = __floats2half2_rn(a, b);
    float2 F = __half22float2(H);
    __half2 L = __floats2half2_rn(a - F.x, b - F.y);
    hi = *reinterpret_cast<const uint32_t*>(&H);
    lo = *reinterpret_cast<const uint32_t*>(&L);
}

// ---------------------------------------------------------------------------
// fp16x2 GEMM, 3-stage ring, one sync per iteration.
// C = (Ah+Al)[M,2048] @ (B[N,2048])^T
// MODE 0: QKV routed; MODE 1: fp32 out ldc=2048.
// ---------------------------------------------------------------------------
template <int MODE>
__global__ __launch_bounds__(256, 2) void gemm_f16(
    const __half* __restrict__ Ah, const __half* __restrict__ Al,
    const __half* __restrict__ Bh,
    __half* __restrict__ Qhi, __half* __restrict__ Qlo,
    __half* __restrict__ KVo, float* __restrict__ Cf)
{
    extern __shared__ __half sm[];
    const uint32_t sb = smem_u32(sm);

    const int tid = threadIdx.x, lane = tid & 31, warp = tid >> 5;
    const int wm0 = (warp >> 2) * 64;
    const int wn0 = (warp & 3) * 32;
    const int m0 = blockIdx.y * BM, n0 = blockIdx.x * BN;

    float acc[4][4][4] = {};
    const int ar = tid >> 2;
    const int ac = (tid & 3) * 8;

    auto ld_stage = [&](int kt, int s) {
        const uint32_t st = sb + (uint32_t)s * GSTAGE;
#pragma unroll
        for (int i = 0; i < 2; i++) {
            int r = ar + i * 64;
            long long go = (long long)(m0 + r) * HIDDEN + kt + ac;
            uint32_t so = (uint32_t)(r * ASTR + ac) * 2;
            cpa16(st + so,             Ah + go);
            cpa16(st + ASZ*2 + so,     Al + go);
            long long gb = (long long)(n0 + r) * HIDDEN + kt + ac;
            cpa16(st + 2*ASZ*2 + so,   Bh + gb);
        }
    };

    const int T = HIDDEN / BKb;           // 64
    ld_stage(0, 0);
    asm volatile("cp.async.commit_group;");
    ld_stage(BKb, 1);
    asm volatile("cp.async.commit_group;");

    for (int t = 0; t < T; t++) {
        if (t + 1 < T) {
            asm volatile("cp.async.wait_group 1;");
        } else {
            asm volatile("cp.async.wait_group 0;");
        }
        __syncthreads();
        if (t + 2 < T) {
            ld_stage((t + 2) * BKb, (t + 2) % 3);
            asm volatile("cp.async.commit_group;");
        }

        const uint32_t st = sb + (uint32_t)(t % 3) * GSTAGE;
        const uint32_t aH0 = st;
        const uint32_t aL0 = st + ASZ*2;
        const uint32_t bH0 = st + 2*ASZ*2;

#pragma unroll
        for (int kk = 0; kk < BKb; kk += 16) {
            uint32_t ah[4][4], al[4][4];
            const int arow = wm0 + (lane & 15);
            const int acol = kk + ((lane >> 4) << 3);
#pragma unroll
            for (int mi = 0; mi < 4; mi++) {
                uint32_t off = (uint32_t)((arow + mi*16) * ASTR + acol) * 2;
                ldm4(ah[mi], aH0 + off);
                ldm4(al[mi], aL0 + off);
            }
            uint32_t bh[4][2];
            const int br = wn0 + ((lane >> 4) << 3) + (lane & 7);
            const int bc = kk + (((lane >> 3) & 1) << 3);
#pragma unroll
            for (int j = 0; j < 2; j++) {
                uint32_t off = (uint32_t)((br + j*16) * ASTR + bc) * 2;
                uint32_t r4[4];
                ldm4(r4, bH0 + off);
                bh[2*j][0]=r4[0]; bh[2*j][1]=r4[1]; bh[2*j+1][0]=r4[2]; bh[2*j+1][1]=r4[3];
            }
#pragma unroll
            for (int mi = 0; mi < 4; mi++)
#pragma unroll
                for (int ni = 0; ni < 4; ni++) {
                    mma16(acc[mi][ni], ah[mi], bh[ni]);
                    mma16(acc[mi][ni], al[mi], bh[ni]);
                }
        }
    }

    const int lr = lane >> 2, lc = lane & 3;
    if (MODE == 0) {
        const bool isQ = (n0 < HIDDEN);
        if (isQ) {
#pragma unroll
            for (int mi = 0; mi < 4; mi++)
#pragma unroll
                for (int ni = 0; ni < 4; ni++) {
                    const int row = m0 + wm0 + mi*16 + lr;
                    const int col = n0 + wn0 + ni*8 + 2*lc;
#pragma unroll
                    for (int hf = 0; hf < 2; hf++) {
                        uint32_t hh, ll;
                        packpair(acc[mi][ni][2*hf], acc[mi][ni][2*hf + 1], hh, ll);
                        long long o = (long long)(row + 8*hf) * HIDDEN + col;
                        *(uint32_t*)(Qhi + o) = hh;
                        *(uint32_t*)(Qlo + o) = ll;
                    }
                }
        } else {
            const int cb = n0 - HIDDEN;
#pragma unroll
            for (int mi = 0; mi < 4; mi++)
#pragma unroll
                for (int ni = 0; ni < 4; ni++) {
                    const int row = m0 + wm0 + mi*16 + lr;
                    const int col = cb + wn0 + ni*8 + 2*lc;
#pragma unroll
                    for (int hf = 0; hf < 2; hf++) {
                        __half2 hv = __floats2half2_rn(acc[mi][ni][2*hf],
                                                       acc[mi][ni][2*hf + 1]);
                        long long o = (long long)(row + 8*hf) * KVLD + col;
                        *(__half2*)(KVo + o) = hv;
                    }
                }
        }
    } else {
#pragma unroll
        for (int mi = 0; mi < 4; mi++)
#pragma unroll
            for (int ni = 0; ni < 4; ni++) {
                const int row = m0 + wm0 + mi*16 + lr;
                const int col = n0 + wn0 + ni*8 + 2*lc;
                long long o = (long long)row * HIDDEN + col;
                *(float2*)(Cf + o) = make_float2(acc[mi][ni][0], acc[mi][ni][1]);
                *(float2*)(Cf + o + 8LL * HIDDEN) =
                    make_float2(acc[mi][ni][2], acc[mi][ni][3]);
            }
    }
}

// ------------------------- split / round kernels ----------------------------
__global__ __launch_bounds__(256) void splitk(
    const float* __restrict__ in, __half* __restrict__ hi,
    __half* __restrict__ lo, int n4)
{
    int i = blockIdx.x * 256 + threadIdx.x;
    if (i >= n4) return;
    float4 v = ((const float4*)in)[i];
    uint32_t h0, l0, h1, l1;
    packpair(v.x, v.y, h0, l0);
    packpair(v.z, v.w, h1, l1);
    ((uint32_t*)hi)[2*i]     = h0;
    ((uint32_t*)hi)[2*i + 1] = h1;
    ((uint32_t*)lo)[2*i]     = l0;
    ((uint32_t*)lo)[2*i + 1] = l1;
}

__global__ __launch_bounds__(256) void roundk(
    const float* __restrict__ in, __half* __restrict__ out, int n4)
{
    int i = blockIdx.x * 256 + threadIdx.x;
    if (i >= n4) return;
    float4 v = ((const float4*)in)[i];
    ((__half2*)out)[2*i]     = __floats2half2_rn(v.x, v.y);
    ((__half2*)out)[2*i + 1] = __floats2half2_rn(v.z, v.w);
}

__global__ __launch_bounds__(256) void splitw_qkv(
    const float* __restrict__ qw, const float* __restrict__ kw,
    const float* __restrict__ vw, __half* __restrict__ w)
{
    int i = blockIdx.x * 256 + threadIdx.x;
    if (i >= NQKV * HIDDEN / 4) return;
    long long e = (long long)i * 4;
    int r = (int)(e >> 11);
    int c = (int)(e & 2047);
    const float* src;
    float sc = 1.0f;
    if (r < 2048)      { src = qw + ((long long)r << 11) + c; sc = QSCALE; }
    else if (r < 2176) { src = kw + ((long long)(r - 2048) << 11) + c; }
    else               { src = vw + ((long long)(r - 2176) << 11) + c; }
    float4 v = *(const float4*)src;
    ((__half2*)w)[2*i]     = __floats2half2_rn(v.x * sc, v.y * sc);
    ((__half2*)w)[2*i + 1] = __floats2half2_rn(v.z * sc, v.w * sc);
}

// ---------------------------------------------------------------------------
// Flash attention: K and V both double-buffered; one __syncthreads per
// iteration, no mid-loop barrier. K(t+1)+V(t+1) prefetched as one group at
// the top of iteration t (full iteration of flight).
// ---------------------------------------------------------------------------
__global__ __launch_bounds__(256, 1) void flash_attn(
    const __half* __restrict__ Qh_, const __half* __restrict__ Ql_,
    const __half* __restrict__ KV_,
    __half* __restrict__ Oh_, __half* __restrict__ Ol_)
{
    extern __shared__ __half fsm[];
    const int b = blockIdx.y >> 4, h = blockIdx.y & 15;
    const int q0 = blockIdx.x * TQ;
    const int tid = threadIdx.x, lane = tid & 31, warp = tid >> 5;
    const int lr = lane >> 2, lc = lane & 3;

    const uint32_t s0 = smem_u32(fsm);
    const uint32_t sK[2] = {s0, s0 + FTB};
    const uint32_t sV[2] = {s0 + 2*FTB, s0 + 3*FTB};

    // ---- stage Q (via K planes), hoist to registers ----
#pragma unroll
    for (int i = 0; i < 8; i++) {
        int id = tid + i * 256;
        int r = id >> 4, c = (id & 15) * 8;
        uint32_t so = (uint32_t)(r * FSTR + c) * 2;
        long long gq = (long long)(b * SS + q0 + r) * HIDDEN + h * DD + c;
        cpa16(sK[0] + so, Qh_ + gq);
        cpa16(sK[1] + so, Ql_ + gq);
    }
    asm volatile("cp.async.commit_group;");
    asm volatile("cp.async.wait_group 0;");
    __syncthreads();

    uint32_t qhr[8][4], qlr[8][4];
#pragma unroll
    for (int kk = 0; kk < 8; kk++) {
        uint32_t aoff = (uint32_t)((warp*16 + (lane & 15)) * FSTR
                                   + kk*16 + ((lane >> 4) << 3)) * 2;
        ldm4(qhr[kk], sK[0] + aoff);
        ldm4(qlr[kk], sK[1] + aoff);
    }
    __syncthreads();

    // ---- prefetch K(0)+V(0) as one group ----
#pragma unroll
    for (int i = 0; i < 8; i++) {
        int id = tid + i * 256;
        int r = id >> 4, c = (id & 15) * 8;
        uint32_t so = (uint32_t)(r * FSTR + c) * 2;
        long long g = (long long)(b * SS + r) * KVLD + c;
        cpa16(sK[0] + so, KV_ + g);
        cpa16(sV[0] + so, KV_ + g + 128);
    }
    asm volatile("cp.async.commit_group;");

    float oacc[16][4] = {};
    float mrow[2] = {-1e30f, -1e30f};
    float lrow[2] = {0.f, 0.f};

    const int TT = SS / TK;
    for (int t = 0; t < TT; t++) {
        asm volatile("cp.async.wait_group 0;");   // K(t)+V(t) landed
        __syncthreads();                           // all warps past t-1 buffers

        // prefetch K(t+1)+V(t+1) into the other buffers (overlap whole iter)
        if (t + 1 < TT) {
            const int nb = (t + 1) & 1;
#pragma unroll
            for (int i = 0; i < 8; i++) {
                int id = tid + i * 256;
                int r = id >> 4, c = (id & 15) * 8;
                uint32_t so = (uint32_t)(r * FSTR + c) * 2;
                long long g = (long long)(b * SS + (t + 1) * TK + r) * KVLD + c;
                cpa16(sK[nb] + so, KV_ + g);
                cpa16(sV[nb] + so, KV_ + g + 128);
            }
            asm volatile("cp.async.commit_group;");
        }

        const uint32_t sKh = sK[t & 1];
        const uint32_t sVh = sV[t & 1];

        // ---- S = Q K^T (log2 domain) ----
        float sacc[16][4] = {};
#pragma unroll
        for (int kk = 0; kk < 8; kk++) {
#pragma unroll
            for (int j = 0; j < 8; j++) {
                uint32_t boff = (uint32_t)((j*16 + ((lane >> 4) << 3) + (lane & 7)) * FSTR
                                           + kk*16 + (((lane >> 3) & 1) << 3)) * 2;
                uint32_t kh4[4];
                ldm4(kh4, sKh + boff);
                mma16(sacc[2*j],   qhr[kk], kh4);     mma16(sacc[2*j],   qlr[kk], kh4);
                mma16(sacc[2*j+1], qhr[kk], kh4 + 2); mma16(sacc[2*j+1], qlr[kk], kh4 + 2);
            }
        }

        // ---- row max + rescale ----
        float tm0 = -1e30f, tm1 = -1e30f;
#pragma unroll
        for (int ni = 0; ni < 16; ni++) {
            tm0 = fmaxf(tm0, fmaxf(sacc[ni][0], sacc[ni][1]));
            tm1 = fmaxf(tm1, fmaxf(sacc[ni][2], sacc[ni][3]));
        }
        tm0 = fmaxf(tm0, __shfl_xor_sync(0xffffffffu, tm0, 1));
        tm0 = fmaxf(tm0, __shfl_xor_sync(0xffffffffu, tm0, 2));
        tm1 = fmaxf(tm1, __shfl_xor_sync(0xffffffffu, tm1, 1));
        tm1 = fmaxf(tm1, __shfl_xor_sync(0xffffffffu, tm1, 2));
        const float mn0 = fmaxf(mrow[0], tm0), mn1 = fmaxf(mrow[1], tm1);
        const float f0 = exp2f(mrow[0] - mn0), f1 = exp2f(mrow[1] - mn1);
        mrow[0] = mn0; mrow[1] = mn1;
#pragma unroll
        for (int nd = 0; nd < 16; nd++) {
            oacc[nd][0] *= f0; oacc[nd][1] *= f0;
            oacc[nd][2] *= f1; oacc[nd][3] *= f1;
        }

        // ---- PV with exp/pack interleaved (V already resident) ----
        float rs0 = 0.f, rs1 = 0.f;
#pragma unroll
        for (int c = 0; c < 8; c++) {
            float e00 = exp2f(sacc[2*c][0]   - mn0);
            float e01 = exp2f(sacc[2*c][1]   - mn0);
            float e02 = exp2f(sacc[2*c][2]   - mn1);
            float e03 = exp2f(sacc[2*c][3]   - mn1);
            float e10 = exp2f(sacc[2*c+1][0] - mn0);
            float e11 = exp2f(sacc[2*c+1][1] - mn0);
            float e12 = exp2f(sacc[2*c+1][2] - mn1);
            float e13 = exp2f(sacc[2*c+1][3] - mn1);
            rs0 += (e00 + e01) + (e10 + e11);
            rs1 += (e02 + e03) + (e12 + e13);
            uint32_t ph4[4], pl4[4];
            packpair(e00, e01, ph4[0], pl4[0]);
            packpair(e02, e03, ph4[1], pl4[1]);
            packpair(e10, e11, ph4[2], pl4[2]);
            packpair(e12, e13, ph4[3], pl4[3]);
#pragma unroll
            for (int j = 0; j < 8; j++) {
                uint32_t boff = (uint32_t)((c*16 + (((lane >> 3) & 1) << 3) + (lane & 7)) * FSTR
                                           + j*16 + ((lane >> 4) << 3)) * 2;
                uint32_t vh4[4];
                ldm4t(vh4, sVh + boff);
                mma16(oacc[2*j],   ph4, vh4);     mma16(oacc[2*j],   pl4, vh4);
                mma16(oacc[2*j+1], ph4, vh4 + 2); mma16(oacc[2*j+1], pl4, vh4 + 2);
            }
        }
        rs0 += __shfl_xor_sync(0xffffffffu, rs0, 1);
        rs0 += __shfl_xor_sync(0xffffffffu, rs0, 2);
        rs1 += __shfl_xor_sync(0xffffffffu, rs1, 1);
        rs1 += __shfl_xor_sync(0xffffffffu, rs1, 2);
        lrow[0] = lrow[0] * f0 + rs0;
        lrow[1] = lrow[1] * f1 + rs1;
    }

    // ---- epilogue ----
    const float i0 = 1.f / lrow[0], i1 = 1.f / lrow[1];
    const long long orow0 = (long long)(b * SS + q0 + warp*16 + lr) * HIDDEN + h * DD;
    const long long orow1 = orow0 + 8LL * HIDDEN;
#pragma unroll
    for (int nd = 0; nd < 16; nd++) {
        const int col = nd * 8 + 2 * lc;
        uint32_t hh, ll;
        packpair(oacc[nd][0] * i0, oacc[nd][1] * i0, hh, ll);
        *(uint32_t*)(Oh_ + orow0 + col) = hh;
        *(uint32_t*)(Ol_ + orow0 + col) = ll;
        packpair(oacc[nd][2] * i1, oacc[nd][3] * i1, hh, ll);
        *(uint32_t*)(Oh_ + orow1 + col) = hh;
        *(uint32_t*)(Ol_ + orow1 + col) = ll;
    }
}

// ---------------------------------------------------------------------------

extern "C" void kernel_launch(void* const* d_in, const int* in_sizes, int n_in,
                              void* d_out, int out_size) {
    const float* x  = (const float*)d_in[0];
    const float* qw = (const float*)d_in[1];
    const float* kw = (const float*)d_in[2];
    const float* vw = (const float*)d_in[3];
    const float* ow = (const float*)d_in[4];
    float* out = (float*)d_out;

    __half *xh,*xl,*w,*owp,*qh,*ql,*kv,*ath,*atl;
    cudaGetSymbolAddress((void**)&xh,  g_xh);  cudaGetSymbolAddress((void**)&xl,  g_xl);
    cudaGetSymbolAddress((void**)&w,   g_w);   cudaGetSymbolAddress((void**)&owp, g_ow);
    cudaGetSymbolAddress((void**)&qh,  g_qh);  cudaGetSymbolAddress((void**)&ql,  g_ql);
    cudaGetSymbolAddress((void**)&kv,  g_kv);
    cudaGetSymbolAddress((void**)&ath, g_ath); cudaGetSymbolAddress((void**)&atl, g_atl);

    cudaFuncSetAttribute((const void*)gemm_f16<0>,
                         cudaFuncAttributeMaxDynamicSharedMemorySize, SMEM_NK);
    cudaFuncSetAttribute((const void*)gemm_f16<1>,
                         cudaFuncAttributeMaxDynamicSharedMemorySize, SMEM_NK);
    cudaFuncSetAttribute((const void*)flash_attn,
                         cudaFuncAttributeMaxDynamicSharedMemorySize, FSMEM);

    // 0) splits / rounds
    splitk<<<(BB*SS*HIDDEN/4 + 255)/256, 256>>>(x, xh, xl, BB*SS*HIDDEN/4);
    splitw_qkv<<<(NQKV*HIDDEN/4 + 255)/256, 256>>>(qw, kw, vw, w);
    roundk<<<(HIDDEN*HIDDEN/4 + 255)/256, 256>>>(ow, owp, HIDDEN*HIDDEN/4);

    // 1) fused QKV projection
    gemm_f16<0><<<dim3(NQKV/BN, (BB*SS)/BM), 256, SMEM_NK>>>(
        xh, xl, w, qh, ql, kv, nullptr);

    // 2) fused attention
    flash_attn<<<dim3(SS/TQ, BB*HEADS), 256, FSMEM>>>(
        qh, ql, kv, ath, atl);

    // 3) out = attn @ Ow^T
    gemm_f16<1><<<dim3(HIDDEN/BN, (BB*SS)/BM), 256, SMEM_NK>>>(
        ath, atl, owp, nullptr, nullptr, nullptr, out);
}

// round 9
// speedup vs baseline: 1.1261x; 1.1261x over previous
#include <cuda_runtime.h>
#include <cuda_fp16.h>
#include <cstdint>

// ---------------------------------------------------------------------------
// ProductionFastMQA round 9:
//   * O-projection: UNSPLIT fp16 A operand (1 MMA per k16) — halves O-proj
//     MMA count; flash epilogue writes single fp16 attn
//   * prep (x-split, w-pack, ow-round) fused into one launch
//   * QKV GEMM + flash unchanged from round 8
// ---------------------------------------------------------------------------

#define HIDDEN   2048
#define HEADS    16
#define HEAD_DIM 128
#define BB       2
#define SS       2048
#define SCALE    0.08838834764831845f
#define LOG2E    1.4426950408889634f
#define QSCALE   (SCALE * LOG2E)
#define NQKV     2304
#define KVLD     256

// gemm tiles
#define BM   128
#define BN   128
#define BKb  32
#define ASTR (BKb + 8)            // 40 halves
#define ASZ  (BM * ASTR)          // 5120 halves

// flash tiles
#define TQ 128
#define TK 128
#define DD 128
#define FSTR 136
#define FTB  (TQ * FSTR * 2)
#define FSMEM (4 * FTB)           // K0 K1 V0 V1

// prep grid regions (blocks of 256 threads, 4 floats/thread)
#define PREP_X_BLKS   8192        // 2*2048*2048/4/256
#define PREP_W_BLKS   4608        // 2304*2048/4/256
#define PREP_OW_BLKS  4096        // 2048*2048/4/256

// ----------------------------- scratch -------------------------------------
__device__ __half g_xh[BB*SS*HIDDEN],  g_xl[BB*SS*HIDDEN];
__device__ __half g_w[NQKV*HIDDEN];
__device__ __half g_ow[HIDDEN*HIDDEN];
__device__ __half g_qh[BB*SS*HIDDEN],  g_ql[BB*SS*HIDDEN];
__device__ __half g_kv[BB*SS*KVLD];
__device__ __half g_at[BB*SS*HIDDEN];          // attn, single fp16

// ----------------------------- PTX helpers ---------------------------------
__device__ __forceinline__ uint32_t smem_u32(const void* p) {
    uint32_t a;
    asm("{ .reg .u64 t; cvta.to.shared.u64 t, %1; cvt.u32.u64 %0, t; }"
        : "=r"(a) : "l"(p));
    return a;
}
__device__ __forceinline__ void ldm4(uint32_t* r, uint32_t a) {
    asm volatile("ldmatrix.sync.aligned.m8n8.x4.shared.b16 {%0,%1,%2,%3},[%4];"
                 : "=r"(r[0]), "=r"(r[1]), "=r"(r[2]), "=r"(r[3]) : "r"(a));
}
__device__ __forceinline__ void ldm4t(uint32_t* r, uint32_t a) {
    asm volatile("ldmatrix.sync.aligned.m8n8.x4.trans.shared.b16 {%0,%1,%2,%3},[%4];"
                 : "=r"(r[0]), "=r"(r[1]), "=r"(r[2]), "=r"(r[3]) : "r"(a));
}
__device__ __forceinline__ void cpa16(uint32_t d, const void* s) {
    asm volatile("cp.async.cg.shared.global [%0],[%1],16;" :: "r"(d), "l"(s));
}
__device__ __forceinline__ void mma16(float* c, const uint32_t* a, const uint32_t* b) {
    asm volatile(
        "mma.sync.aligned.m16n8k16.row.col.f32.f16.f16.f32 "
        "{%0,%1,%2,%3},{%4,%5,%6,%7},{%8,%9},{%0,%1,%2,%3};"
        : "+f"(c[0]), "+f"(c[1]), "+f"(c[2]), "+f"(c[3])
        : "r"(a[0]), "r"(a[1]), "r"(a[2]), "r"(a[3]), "r"(b[0]), "r"(b[1]));
}
__device__ __forceinline__ void packpair(float a, float b, uint32_t& hi, uint32_t& lo) {
    __half2 H = __floats2half2_rn(a, b);
    float2 F = __half22float2(H);
    __half2 L = __floats2half2_rn(a - F.x, b - F.y);
    hi = *reinterpret_cast<const uint32_t*>(&H);
    lo = *reinterpret_cast<const uint32_t*>(&L);
}

// ---------------------------------------------------------------------------
// fp16 GEMM, 3-stage ring.  C = A[M,2048] @ (B[N,2048])^T
// MODE 0: A split hi/lo (2 MMAs/k16), outputs routed Q-pair / KV-single.
// MODE 1: A single plane (1 MMA/k16), fp32 output ldc=2048.
// ---------------------------------------------------------------------------
template <int MODE>
__global__ __launch_bounds__(256, 2) void gemm_f16(
    const __half* __restrict__ Ah, const __half* __restrict__ Al,
    const __half* __restrict__ Bh,
    __half* __restrict__ Qhi, __half* __restrict__ Qlo,
    __half* __restrict__ KVo, float* __restrict__ Cf)
{
    constexpr int NPL = (MODE == 0) ? 3 : 2;       // planes per stage
    constexpr uint32_t GST = NPL * ASZ * 2;        // stage bytes
    extern __shared__ __half sm[];
    const uint32_t sb = smem_u32(sm);

    const int tid = threadIdx.x, lane = tid & 31, warp = tid >> 5;
    const int wm0 = (warp >> 2) * 64;
    const int wn0 = (warp & 3) * 32;
    const int m0 = blockIdx.y * BM, n0 = blockIdx.x * BN;

    float acc[4][4][4] = {};
    const int ar = tid >> 2;
    const int ac = (tid & 3) * 8;

    auto ld_stage = [&](int kt, int s) {
        const uint32_t st = sb + (uint32_t)s * GST;
#pragma unroll
        for (int i = 0; i < 2; i++) {
            int r = ar + i * 64;
            long long go = (long long)(m0 + r) * HIDDEN + kt + ac;
            uint32_t so = (uint32_t)(r * ASTR + ac) * 2;
            cpa16(st + so, Ah + go);
            if (MODE == 0) cpa16(st + ASZ*2 + so, Al + go);
            long long gb = (long long)(n0 + r) * HIDDEN + kt + ac;
            cpa16(st + (NPL-1)*ASZ*2 + so, Bh + gb);
        }
    };

    const int T = HIDDEN / BKb;
    ld_stage(0, 0);
    asm volatile("cp.async.commit_group;");
    ld_stage(BKb, 1);
    asm volatile("cp.async.commit_group;");

    for (int t = 0; t < T; t++) {
        if (t + 1 < T) {
            asm volatile("cp.async.wait_group 1;");
        } else {
            asm volatile("cp.async.wait_group 0;");
        }
        __syncthreads();
        if (t + 2 < T) {
            ld_stage((t + 2) * BKb, (t + 2) % 3);
            asm volatile("cp.async.commit_group;");
        }

        const uint32_t st = sb + (uint32_t)(t % 3) * GST;
        const uint32_t aH0 = st;
        const uint32_t aL0 = st + ASZ*2;
        const uint32_t bH0 = st + (NPL-1)*ASZ*2;

#pragma unroll
        for (int kk = 0; kk < BKb; kk += 16) {
            uint32_t ah[4][4], al[4][4];
            const int arow = wm0 + (lane & 15);
            const int acol = kk + ((lane >> 4) << 3);
#pragma unroll
            for (int mi = 0; mi < 4; mi++) {
                uint32_t off = (uint32_t)((arow + mi*16) * ASTR + acol) * 2;
                ldm4(ah[mi], aH0 + off);
                if (MODE == 0) ldm4(al[mi], aL0 + off);
            }
            uint32_t bh[4][2];
            const int br = wn0 + ((lane >> 4) << 3) + (lane & 7);
            const int bc = kk + (((lane >> 3) & 1) << 3);
#pragma unroll
            for (int j = 0; j < 2; j++) {
                uint32_t off = (uint32_t)((br + j*16) * ASTR + bc) * 2;
                uint32_t r4[4];
                ldm4(r4, bH0 + off);
                bh[2*j][0]=r4[0]; bh[2*j][1]=r4[1]; bh[2*j+1][0]=r4[2]; bh[2*j+1][1]=r4[3];
            }
#pragma unroll
            for (int mi = 0; mi < 4; mi++)
#pragma unroll
                for (int ni = 0; ni < 4; ni++) {
                    mma16(acc[mi][ni], ah[mi], bh[ni]);
                    if (MODE == 0) mma16(acc[mi][ni], al[mi], bh[ni]);
                }
        }
    }

    const int lr = lane >> 2, lc = lane & 3;
    if (MODE == 0) {
        const bool isQ = (n0 < HIDDEN);
        if (isQ) {
#pragma unroll
            for (int mi = 0; mi < 4; mi++)
#pragma unroll
                for (int ni = 0; ni < 4; ni++) {
                    const int row = m0 + wm0 + mi*16 + lr;
                    const int col = n0 + wn0 + ni*8 + 2*lc;
#pragma unroll
                    for (int hf = 0; hf < 2; hf++) {
                        uint32_t hh, ll;
                        packpair(acc[mi][ni][2*hf], acc[mi][ni][2*hf + 1], hh, ll);
                        long long o = (long long)(row + 8*hf) * HIDDEN + col;
                        *(uint32_t*)(Qhi + o) = hh;
                        *(uint32_t*)(Qlo + o) = ll;
                    }
                }
        } else {
            const int cb = n0 - HIDDEN;
#pragma unroll
            for (int mi = 0; mi < 4; mi++)
#pragma unroll
                for (int ni = 0; ni < 4; ni++) {
                    const int row = m0 + wm0 + mi*16 + lr;
                    const int col = cb + wn0 + ni*8 + 2*lc;
#pragma unroll
                    for (int hf = 0; hf < 2; hf++) {
                        __half2 hv = __floats2half2_rn(acc[mi][ni][2*hf],
                                                       acc[mi][ni][2*hf + 1]);
                        long long o = (long long)(row + 8*hf) * KVLD + col;
                        *(__half2*)(KVo + o) = hv;
                    }
                }
        }
    } else {
#pragma unroll
        for (int mi = 0; mi < 4; mi++)
#pragma unroll
            for (int ni = 0; ni < 4; ni++) {
                const int row = m0 + wm0 + mi*16 + lr;
                const int col = n0 + wn0 + ni*8 + 2*lc;
                long long o = (long long)row * HIDDEN + col;
                *(float2*)(Cf + o) = make_float2(acc[mi][ni][0], acc[mi][ni][1]);
                *(float2*)(Cf + o + 8LL * HIDDEN) =
                    make_float2(acc[mi][ni][2], acc[mi][ni][3]);
            }
    }
}

// ------------------------- fused prep kernel --------------------------------
// region [0, PREP_X_BLKS): x -> xh/xl split
// region [.., +PREP_W_BLKS): [Qw*QSCALE; Kw; Vw] -> fp16 pack
// region [.., +PREP_OW_BLKS): ow -> fp16 round
__global__ __launch_bounds__(256) void prep(
    const float* __restrict__ x,  const float* __restrict__ qw,
    const float* __restrict__ kw, const float* __restrict__ vw,
    const float* __restrict__ ow,
    __half* __restrict__ xh, __half* __restrict__ xl,
    __half* __restrict__ w,  __half* __restrict__ owp)
{
    const int bid = blockIdx.x;
    if (bid < PREP_X_BLKS) {
        int i = bid * 256 + threadIdx.x;
        float4 v = ((const float4*)x)[i];
        uint32_t h0, l0, h1, l1;
        packpair(v.x, v.y, h0, l0);
        packpair(v.z, v.w, h1, l1);
        ((uint32_t*)xh)[2*i]     = h0;
        ((uint32_t*)xh)[2*i + 1] = h1;
        ((uint32_t*)xl)[2*i]     = l0;
        ((uint32_t*)xl)[2*i + 1] = l1;
    } else if (bid < PREP_X_BLKS + PREP_W_BLKS) {
        int i = (bid - PREP_X_BLKS) * 256 + threadIdx.x;
        long long e = (long long)i * 4;
        int r = (int)(e >> 11);
        int c = (int)(e & 2047);
        const float* src;
        float sc = 1.0f;
        if (r < 2048)      { src = qw + ((long long)r << 11) + c; sc = QSCALE; }
        else if (r < 2176) { src = kw + ((long long)(r - 2048) << 11) + c; }
        else               { src = vw + ((long long)(r - 2176) << 11) + c; }
        float4 v = *(const float4*)src;
        ((__half2*)w)[2*i]     = __floats2half2_rn(v.x * sc, v.y * sc);
        ((__half2*)w)[2*i + 1] = __floats2half2_rn(v.z * sc, v.w * sc);
    } else {
        int i = (bid - PREP_X_BLKS - PREP_W_BLKS) * 256 + threadIdx.x;
        float4 v = ((const float4*)ow)[i];
        ((__half2*)owp)[2*i]     = __floats2half2_rn(v.x, v.y);
        ((__half2*)owp)[2*i + 1] = __floats2half2_rn(v.z, v.w);
    }
}

// ---------------------------------------------------------------------------
// Flash attention (round 8 structure); epilogue writes SINGLE fp16 attn.
// ---------------------------------------------------------------------------
__global__ __launch_bounds__(256, 1) void flash_attn(
    const __half* __restrict__ Qh_, const __half* __restrict__ Ql_,
    const __half* __restrict__ KV_, __half* __restrict__ O_)
{
    extern __shared__ __half fsm[];
    const int b = blockIdx.y >> 4, h = blockIdx.y & 15;
    const int q0 = blockIdx.x * TQ;
    const int tid = threadIdx.x, lane = tid & 31, warp = tid >> 5;
    const int lr = lane >> 2, lc = lane & 3;

    const uint32_t s0 = smem_u32(fsm);
    const uint32_t sK[2] = {s0, s0 + FTB};
    const uint32_t sV[2] = {s0 + 2*FTB, s0 + 3*FTB};

    // ---- stage Q (via K planes), hoist to registers ----
#pragma unroll
    for (int i = 0; i < 8; i++) {
        int id = tid + i * 256;
        int r = id >> 4, c = (id & 15) * 8;
        uint32_t so = (uint32_t)(r * FSTR + c) * 2;
        long long gq = (long long)(b * SS + q0 + r) * HIDDEN + h * DD + c;
        cpa16(sK[0] + so, Qh_ + gq);
        cpa16(sK[1] + so, Ql_ + gq);
    }
    asm volatile("cp.async.commit_group;");
    asm volatile("cp.async.wait_group 0;");
    __syncthreads();

    uint32_t qhr[8][4], qlr[8][4];
#pragma unroll
    for (int kk = 0; kk < 8; kk++) {
        uint32_t aoff = (uint32_t)((warp*16 + (lane & 15)) * FSTR
                                   + kk*16 + ((lane >> 4) << 3)) * 2;
        ldm4(qhr[kk], sK[0] + aoff);
        ldm4(qlr[kk], sK[1] + aoff);
    }
    __syncthreads();

    // ---- prefetch K(0)+V(0) ----
#pragma unroll
    for (int i = 0; i < 8; i++) {
        int id = tid + i * 256;
        int r = id >> 4, c = (id & 15) * 8;
        uint32_t so = (uint32_t)(r * FSTR + c) * 2;
        long long g = (long long)(b * SS + r) * KVLD + c;
        cpa16(sK[0] + so, KV_ + g);
        cpa16(sV[0] + so, KV_ + g + 128);
    }
    asm volatile("cp.async.commit_group;");

    float oacc[16][4] = {};
    float mrow[2] = {-1e30f, -1e30f};
    float lrow[2] = {0.f, 0.f};

    const int TT = SS / TK;
    for (int t = 0; t < TT; t++) {
        asm volatile("cp.async.wait_group 0;");
        __syncthreads();

        if (t + 1 < TT) {
            const int nb = (t + 1) & 1;
#pragma unroll
            for (int i = 0; i < 8; i++) {
                int id = tid + i * 256;
                int r = id >> 4, c = (id & 15) * 8;
                uint32_t so = (uint32_t)(r * FSTR + c) * 2;
                long long g = (long long)(b * SS + (t + 1) * TK + r) * KVLD + c;
                cpa16(sK[nb] + so, KV_ + g);
                cpa16(sV[nb] + so, KV_ + g + 128);
            }
            asm volatile("cp.async.commit_group;");
        }

        const uint32_t sKh = sK[t & 1];
        const uint32_t sVh = sV[t & 1];

        // ---- S = Q K^T (log2 domain) ----
        float sacc[16][4] = {};
#pragma unroll
        for (int kk = 0; kk < 8; kk++) {
#pragma unroll
            for (int j = 0; j < 8; j++) {
                uint32_t boff = (uint32_t)((j*16 + ((lane >> 4) << 3) + (lane & 7)) * FSTR
                                           + kk*16 + (((lane >> 3) & 1) << 3)) * 2;
                uint32_t kh4[4];
                ldm4(kh4, sKh + boff);
                mma16(sacc[2*j],   qhr[kk], kh4);     mma16(sacc[2*j],   qlr[kk], kh4);
                mma16(sacc[2*j+1], qhr[kk], kh4 + 2); mma16(sacc[2*j+1], qlr[kk], kh4 + 2);
            }
        }

        // ---- row max + rescale ----
        float tm0 = -1e30f, tm1 = -1e30f;
#pragma unroll
        for (int ni = 0; ni < 16; ni++) {
            tm0 = fmaxf(tm0, fmaxf(sacc[ni][0], sacc[ni][1]));
            tm1 = fmaxf(tm1, fmaxf(sacc[ni][2], sacc[ni][3]));
        }
        tm0 = fmaxf(tm0, __shfl_xor_sync(0xffffffffu, tm0, 1));
        tm0 = fmaxf(tm0, __shfl_xor_sync(0xffffffffu, tm0, 2));
        tm1 = fmaxf(tm1, __shfl_xor_sync(0xffffffffu, tm1, 1));
        tm1 = fmaxf(tm1, __shfl_xor_sync(0xffffffffu, tm1, 2));
        const float mn0 = fmaxf(mrow[0], tm0), mn1 = fmaxf(mrow[1], tm1);
        const float f0 = exp2f(mrow[0] - mn0), f1 = exp2f(mrow[1] - mn1);
        mrow[0] = mn0; mrow[1] = mn1;
#pragma unroll
        for (int nd = 0; nd < 16; nd++) {
            oacc[nd][0] *= f0; oacc[nd][1] *= f0;
            oacc[nd][2] *= f1; oacc[nd][3] *= f1;
        }

        // ---- PV with exp/pack interleaved ----
        float rs0 = 0.f, rs1 = 0.f;
#pragma unroll
        for (int c = 0; c < 8; c++) {
            float e00 = exp2f(sacc[2*c][0]   - mn0);
            float e01 = exp2f(sacc[2*c][1]   - mn0);
            float e02 = exp2f(sacc[2*c][2]   - mn1);
            float e03 = exp2f(sacc[2*c][3]   - mn1);
            float e10 = exp2f(sacc[2*c+1][0] - mn0);
            float e11 = exp2f(sacc[2*c+1][1] - mn0);
            float e12 = exp2f(sacc[2*c+1][2] - mn1);
            float e13 = exp2f(sacc[2*c+1][3] - mn1);
            rs0 += (e00 + e01) + (e10 + e11);
            rs1 += (e02 + e03) + (e12 + e13);
            uint32_t ph4[4], pl4[4];
            packpair(e00, e01, ph4[0], pl4[0]);
            packpair(e02, e03, ph4[1], pl4[1]);
            packpair(e10, e11, ph4[2], pl4[2]);
            packpair(e12, e13, ph4[3], pl4[3]);
#pragma unroll
            for (int j = 0; j < 8; j++) {
                uint32_t boff = (uint32_t)((c*16 + (((lane >> 3) & 1) << 3) + (lane & 7)) * FSTR
                                           + j*16 + ((lane >> 4) << 3)) * 2;
                uint32_t vh4[4];
                ldm4t(vh4, sVh + boff);
                mma16(oacc[2*j],   ph4, vh4);     mma16(oacc[2*j],   pl4, vh4);
                mma16(oacc[2*j+1], ph4, vh4 + 2); mma16(oacc[2*j+1], pl4, vh4 + 2);
            }
        }
        rs0 += __shfl_xor_sync(0xffffffffu, rs0, 1);
        rs0 += __shfl_xor_sync(0xffffffffu, rs0, 2);
        rs1 += __shfl_xor_sync(0xffffffffu, rs1, 1);
        rs1 += __shfl_xor_sync(0xffffffffu, rs1, 2);
        lrow[0] = lrow[0] * f0 + rs0;
        lrow[1] = lrow[1] * f1 + rs1;
    }

    // ---- epilogue: O /= l, single fp16 write ----
    const float i0 = 1.f / lrow[0], i1 = 1.f / lrow[1];
    const long long orow0 = (long long)(b * SS + q0 + warp*16 + lr) * HIDDEN + h * DD;
    const long long orow1 = orow0 + 8LL * HIDDEN;
#pragma unroll
    for (int nd = 0; nd < 16; nd++) {
        const int col = nd * 8 + 2 * lc;
        __half2 v0 = __floats2half2_rn(oacc[nd][0] * i0, oacc[nd][1] * i0);
        __half2 v1 = __floats2half2_rn(oacc[nd][2] * i1, oacc[nd][3] * i1);
        *(__half2*)(O_ + orow0 + col) = v0;
        *(__half2*)(O_ + orow1 + col) = v1;
    }
}

// ---------------------------------------------------------------------------

extern "C" void kernel_launch(void* const* d_in, const int* in_sizes, int n_in,
                              void* d_out, int out_size) {
    const float* x  = (const float*)d_in[0];
    const float* qw = (const float*)d_in[1];
    const float* kw = (const float*)d_in[2];
    const float* vw = (const float*)d_in[3];
    const float* ow = (const float*)d_in[4];
    float* out = (float*)d_out;

    __half *xh,*xl,*w,*owp,*qh,*ql,*kv,*at;
    cudaGetSymbolAddress((void**)&xh,  g_xh);  cudaGetSymbolAddress((void**)&xl,  g_xl);
    cudaGetSymbolAddress((void**)&w,   g_w);   cudaGetSymbolAddress((void**)&owp, g_ow);
    cudaGetSymbolAddress((void**)&qh,  g_qh);  cudaGetSymbolAddress((void**)&ql,  g_ql);
    cudaGetSymbolAddress((void**)&kv,  g_kv);  cudaGetSymbolAddress((void**)&at,  g_at);

    const int SMEM0 = 3 * (3 * ASZ * 2);   // 92160 (split A)
    const int SMEM1 = 3 * (2 * ASZ * 2);   // 61440 (single A)
    cudaFuncSetAttribute((const void*)gemm_f16<0>,
                         cudaFuncAttributeMaxDynamicSharedMemorySize, SMEM0);
    cudaFuncSetAttribute((const void*)gemm_f16<1>,
                         cudaFuncAttributeMaxDynamicSharedMemorySize, SMEM1);
    cudaFuncSetAttribute((const void*)flash_attn,
                         cudaFuncAttributeMaxDynamicSharedMemorySize, FSMEM);

    // 0) fused prep
    prep<<<PREP_X_BLKS + PREP_W_BLKS + PREP_OW_BLKS, 256>>>(
        x, qw, kw, vw, ow, xh, xl, w, owp);

    // 1) fused QKV projection (split-A fp16x2)
    gemm_f16<0><<<dim3(NQKV/BN, (BB*SS)/BM), 256, SMEM0>>>(
        xh, xl, w, qh, ql, kv, nullptr);

    // 2) fused attention -> single fp16 attn
    flash_attn<<<dim3(SS/TQ, BB*HEADS), 256, FSMEM>>>(qh, ql, kv, at);

    // 3) out = attn @ Ow^T (single-A fp16, 1 MMA/k16)
    gemm_f16<1><<<dim3(HIDDEN/BN, (BB*SS)/BM), 256, SMEM1>>>(
        at, nullptr, owp, nullptr, nullptr, nullptr, out);
}

// round 11
// speedup vs baseline: 1.2570x; 1.1163x over previous
#include <cuda_runtime.h>
#include <cuda_fp16.h>
#include <cstdint>

// ---------------------------------------------------------------------------
// ProductionFastMQA round 11 (= round 10 resubmitted after infra failure):
//   * flash PV: UNSPLIT P operand (1 MMA per k16) — 25% fewer flash MMAs,
//     half the P-pack work. Q stays split (softmax-exponent sensitivity).
//   * QKV GEMM / O-proj / prep unchanged from round 9.
// ---------------------------------------------------------------------------

#define HIDDEN   2048
#define HEADS    16
#define HEAD_DIM 128
#define BB       2
#define SS       2048
#define SCALE    0.08838834764831845f
#define LOG2E    1.4426950408889634f
#define QSCALE   (SCALE * LOG2E)
#define NQKV     2304
#define KVLD     256

// gemm tiles
#define BM   128
#define BN   128
#define BKb  32
#define ASTR (BKb + 8)            // 40 halves
#define ASZ  (BM * ASTR)          // 5120 halves

// flash tiles
#define TQ 128
#define TK 128
#define DD 128
#define FSTR 136
#define FTB  (TQ * FSTR * 2)
#define FSMEM (4 * FTB)           // K0 K1 V0 V1

// prep grid regions
#define PREP_X_BLKS   8192
#define PREP_W_BLKS   4608
#define PREP_OW_BLKS  4096

// ----------------------------- scratch -------------------------------------
__device__ __half g_xh[BB*SS*HIDDEN],  g_xl[BB*SS*HIDDEN];
__device__ __half g_w[NQKV*HIDDEN];
__device__ __half g_ow[HIDDEN*HIDDEN];
__device__ __half g_qh[BB*SS*HIDDEN],  g_ql[BB*SS*HIDDEN];
__device__ __half g_kv[BB*SS*KVLD];
__device__ __half g_at[BB*SS*HIDDEN];

// ----------------------------- PTX helpers ---------------------------------
__device__ __forceinline__ uint32_t smem_u32(const void* p) {
    uint32_t a;
    asm("{ .reg .u64 t; cvta.to.shared.u64 t, %1; cvt.u32.u64 %0, t; }"
        : "=r"(a) : "l"(p));
    return a;
}
__device__ __forceinline__ void ldm4(uint32_t* r, uint32_t a) {
    asm volatile("ldmatrix.sync.aligned.m8n8.x4.shared.b16 {%0,%1,%2,%3},[%4];"
                 : "=r"(r[0]), "=r"(r[1]), "=r"(r[2]), "=r"(r[3]) : "r"(a));
}
__device__ __forceinline__ void ldm4t(uint32_t* r, uint32_t a) {
    asm volatile("ldmatrix.sync.aligned.m8n8.x4.trans.shared.b16 {%0,%1,%2,%3},[%4];"
                 : "=r"(r[0]), "=r"(r[1]), "=r"(r[2]), "=r"(r[3]) : "r"(a));
}
__device__ __forceinline__ void cpa16(uint32_t d, const void* s) {
    asm volatile("cp.async.cg.shared.global [%0],[%1],16;" :: "r"(d), "l"(s));
}
__device__ __forceinline__ void mma16(float* c, const uint32_t* a, const uint32_t* b) {
    asm volatile(
        "mma.sync.aligned.m16n8k16.row.col.f32.f16.f16.f32 "
        "{%0,%1,%2,%3},{%4,%5,%6,%7},{%8,%9},{%0,%1,%2,%3};"
        : "+f"(c[0]), "+f"(c[1]), "+f"(c[2]), "+f"(c[3])
        : "r"(a[0]), "r"(a[1]), "r"(a[2]), "r"(a[3]), "r"(b[0]), "r"(b[1]));
}
__device__ __forceinline__ void packpair(float a, float b, uint32_t& hi, uint32_t& lo) {
    __half2 H = __floats2half2_rn(a, b);
    float2 F = __half22float2(H);
    __half2 L = __floats2half2_rn(a - F.x, b - F.y);
    hi = *reinterpret_cast<const uint32_t*>(&H);
    lo = *reinterpret_cast<const uint32_t*>(&L);
}
__device__ __forceinline__ uint32_t pack2(float a, float b) {
    __half2 H = __floats2half2_rn(a, b);
    return *reinterpret_cast<const uint32_t*>(&H);
}

// ---------------------------------------------------------------------------
// fp16 GEMM, 3-stage ring (round 9, unchanged).
// MODE 0: A split (2 MMAs/k16), Q-pair / KV-single outputs.
// MODE 1: A single (1 MMA/k16), fp32 out.
// ---------------------------------------------------------------------------
template <int MODE>
__global__ __launch_bounds__(256, 2) void gemm_f16(
    const __half* __restrict__ Ah, const __half* __restrict__ Al,
    const __half* __restrict__ Bh,
    __half* __restrict__ Qhi, __half* __restrict__ Qlo,
    __half* __restrict__ KVo, float* __restrict__ Cf)
{
    constexpr int NPL = (MODE == 0) ? 3 : 2;
    constexpr uint32_t GST = NPL * ASZ * 2;
    extern __shared__ __half sm[];
    const uint32_t sb = smem_u32(sm);

    const int tid = threadIdx.x, lane = tid & 31, warp = tid >> 5;
    const int wm0 = (warp >> 2) * 64;
    const int wn0 = (warp & 3) * 32;
    const int m0 = blockIdx.y * BM, n0 = blockIdx.x * BN;

    float acc[4][4][4] = {};
    const int ar = tid >> 2;
    const int ac = (tid & 3) * 8;

    auto ld_stage = [&](int kt, int s) {
        const uint32_t st = sb + (uint32_t)s * GST;
#pragma unroll
        for (int i = 0; i < 2; i++) {
            int r = ar + i * 64;
            long long go = (long long)(m0 + r) * HIDDEN + kt + ac;
            uint32_t so = (uint32_t)(r * ASTR + ac) * 2;
            cpa16(st + so, Ah + go);
            if (MODE == 0) cpa16(st + ASZ*2 + so, Al + go);
            long long gb = (long long)(n0 + r) * HIDDEN + kt + ac;
            cpa16(st + (NPL-1)*ASZ*2 + so, Bh + gb);
        }
    };

    const int T = HIDDEN / BKb;
    ld_stage(0, 0);
    asm volatile("cp.async.commit_group;");
    ld_stage(BKb, 1);
    asm volatile("cp.async.commit_group;");

    for (int t = 0; t < T; t++) {
        if (t + 1 < T) {
            asm volatile("cp.async.wait_group 1;");
        } else {
            asm volatile("cp.async.wait_group 0;");
        }
        __syncthreads();
        if (t + 2 < T) {
            ld_stage((t + 2) * BKb, (t + 2) % 3);
            asm volatile("cp.async.commit_group;");
        }

        const uint32_t st = sb + (uint32_t)(t % 3) * GST;
        const uint32_t aH0 = st;
        const uint32_t aL0 = st + ASZ*2;
        const uint32_t bH0 = st + (NPL-1)*ASZ*2;

#pragma unroll
        for (int kk = 0; kk < BKb; kk += 16) {
            uint32_t ah[4][4], al[4][4];
            const int arow = wm0 + (lane & 15);
            const int acol = kk + ((lane >> 4) << 3);
#pragma unroll
            for (int mi = 0; mi < 4; mi++) {
                uint32_t off = (uint32_t)((arow + mi*16) * ASTR + acol) * 2;
                ldm4(ah[mi], aH0 + off);
                if (MODE == 0) ldm4(al[mi], aL0 + off);
            }
            uint32_t bh[4][2];
            const int br = wn0 + ((lane >> 4) << 3) + (lane & 7);
            const int bc = kk + (((lane >> 3) & 1) << 3);
#pragma unroll
            for (int j = 0; j < 2; j++) {
                uint32_t off = (uint32_t)((br + j*16) * ASTR + bc) * 2;
                uint32_t r4[4];
                ldm4(r4, bH0 + off);
                bh[2*j][0]=r4[0]; bh[2*j][1]=r4[1]; bh[2*j+1][0]=r4[2]; bh[2*j+1][1]=r4[3];
            }
#pragma unroll
            for (int mi = 0; mi < 4; mi++)
#pragma unroll
                for (int ni = 0; ni < 4; ni++) {
                    mma16(acc[mi][ni], ah[mi], bh[ni]);
                    if (MODE == 0) mma16(acc[mi][ni], al[mi], bh[ni]);
                }
        }
    }

    const int lr = lane >> 2, lc = lane & 3;
    if (MODE == 0) {
        const bool isQ = (n0 < HIDDEN);
        if (isQ) {
#pragma unroll
            for (int mi = 0; mi < 4; mi++)
#pragma unroll
                for (int ni = 0; ni < 4; ni++) {
                    const int row = m0 + wm0 + mi*16 + lr;
                    const int col = n0 + wn0 + ni*8 + 2*lc;
#pragma unroll
                    for (int hf = 0; hf < 2; hf++) {
                        uint32_t hh, ll;
                        packpair(acc[mi][ni][2*hf], acc[mi][ni][2*hf + 1], hh, ll);
                        long long o = (long long)(row + 8*hf) * HIDDEN + col;
                        *(uint32_t*)(Qhi + o) = hh;
                        *(uint32_t*)(Qlo + o) = ll;
                    }
                }
        } else {
            const int cb = n0 - HIDDEN;
#pragma unroll
            for (int mi = 0; mi < 4; mi++)
#pragma unroll
                for (int ni = 0; ni < 4; ni++) {
                    const int row = m0 + wm0 + mi*16 + lr;
                    const int col = cb + wn0 + ni*8 + 2*lc;
#pragma unroll
                    for (int hf = 0; hf < 2; hf++) {
                        long long o = (long long)(row + 8*hf) * KVLD + col;
                        *(uint32_t*)(KVo + o) =
                            pack2(acc[mi][ni][2*hf], acc[mi][ni][2*hf + 1]);
                    }
                }
        }
    } else {
#pragma unroll
        for (int mi = 0; mi < 4; mi++)
#pragma unroll
            for (int ni = 0; ni < 4; ni++) {
                const int row = m0 + wm0 + mi*16 + lr;
                const int col = n0 + wn0 + ni*8 + 2*lc;
                long long o = (long long)row * HIDDEN + col;
                *(float2*)(Cf + o) = make_float2(acc[mi][ni][0], acc[mi][ni][1]);
                *(float2*)(Cf + o + 8LL * HIDDEN) =
                    make_float2(acc[mi][ni][2], acc[mi][ni][3]);
            }
    }
}

// ------------------------- fused prep kernel --------------------------------
__global__ __launch_bounds__(256) void prep(
    const float* __restrict__ x,  const float* __restrict__ qw,
    const float* __restrict__ kw, const float* __restrict__ vw,
    const float* __restrict__ ow,
    __half* __restrict__ xh, __half* __restrict__ xl,
    __half* __restrict__ w,  __half* __restrict__ owp)
{
    const int bid = blockIdx.x;
    if (bid < PREP_X_BLKS) {
        int i = bid * 256 + threadIdx.x;
        float4 v = ((const float4*)x)[i];
        uint32_t h0, l0, h1, l1;
        packpair(v.x, v.y, h0, l0);
        packpair(v.z, v.w, h1, l1);
        ((uint32_t*)xh)[2*i]     = h0;
        ((uint32_t*)xh)[2*i + 1] = h1;
        ((uint32_t*)xl)[2*i]     = l0;
        ((uint32_t*)xl)[2*i + 1] = l1;
    } else if (bid < PREP_X_BLKS + PREP_W_BLKS) {
        int i = (bid - PREP_X_BLKS) * 256 + threadIdx.x;
        long long e = (long long)i * 4;
        int r = (int)(e >> 11);
        int c = (int)(e & 2047);
        const float* src;
        float sc = 1.0f;
        if (r < 2048)      { src = qw + ((long long)r << 11) + c; sc = QSCALE; }
        else if (r < 2176) { src = kw + ((long long)(r - 2048) << 11) + c; }
        else               { src = vw + ((long long)(r - 2176) << 11) + c; }
        float4 v = *(const float4*)src;
        ((uint32_t*)w)[2*i]     = pack2(v.x * sc, v.y * sc);
        ((uint32_t*)w)[2*i + 1] = pack2(v.z * sc, v.w * sc);
    } else {
        int i = (bid - PREP_X_BLKS - PREP_W_BLKS) * 256 + threadIdx.x;
        float4 v = ((const float4*)ow)[i];
        ((uint32_t*)owp)[2*i]     = pack2(v.x, v.y);
        ((uint32_t*)owp)[2*i + 1] = pack2(v.z, v.w);
    }
}

// ---------------------------------------------------------------------------
// Flash attention: Q split (2 MMAs/k16 in S), P UNSPLIT (1 MMA/k16 in PV).
// K/V double-buffered, one sync per iteration.
// ---------------------------------------------------------------------------
__global__ __launch_bounds__(256, 1) void flash_attn(
    const __half* __restrict__ Qh_, const __half* __restrict__ Ql_,
    const __half* __restrict__ KV_, __half* __restrict__ O_)
{
    extern __shared__ __half fsm[];
    const int b = blockIdx.y >> 4, h = blockIdx.y & 15;
    const int q0 = blockIdx.x * TQ;
    const int tid = threadIdx.x, lane = tid & 31, warp = tid >> 5;
    const int lr = lane >> 2, lc = lane & 3;

    const uint32_t s0 = smem_u32(fsm);
    const uint32_t sK[2] = {s0, s0 + FTB};
    const uint32_t sV[2] = {s0 + 2*FTB, s0 + 3*FTB};

    // ---- stage Q (via K planes), hoist to registers ----
#pragma unroll
    for (int i = 0; i < 8; i++) {
        int id = tid + i * 256;
        int r = id >> 4, c = (id & 15) * 8;
        uint32_t so = (uint32_t)(r * FSTR + c) * 2;
        long long gq = (long long)(b * SS + q0 + r) * HIDDEN + h * DD + c;
        cpa16(sK[0] + so, Qh_ + gq);
        cpa16(sK[1] + so, Ql_ + gq);
    }
    asm volatile("cp.async.commit_group;");
    asm volatile("cp.async.wait_group 0;");
    __syncthreads();

    uint32_t qhr[8][4], qlr[8][4];
#pragma unroll
    for (int kk = 0; kk < 8; kk++) {
        uint32_t aoff = (uint32_t)((warp*16 + (lane & 15)) * FSTR
                                   + kk*16 + ((lane >> 4) << 3)) * 2;
        ldm4(qhr[kk], sK[0] + aoff);
        ldm4(qlr[kk], sK[1] + aoff);
    }
    __syncthreads();

    // ---- prefetch K(0)+V(0) ----
#pragma unroll
    for (int i = 0; i < 8; i++) {
        int id = tid + i * 256;
        int r = id >> 4, c = (id & 15) * 8;
        uint32_t so = (uint32_t)(r * FSTR + c) * 2;
        long long g = (long long)(b * SS + r) * KVLD + c;
        cpa16(sK[0] + so, KV_ + g);
        cpa16(sV[0] + so, KV_ + g + 128);
    }
    asm volatile("cp.async.commit_group;");

    float oacc[16][4] = {};
    float mrow[2] = {-1e30f, -1e30f};
    float lrow[2] = {0.f, 0.f};

    const int TT = SS / TK;
    for (int t = 0; t < TT; t++) {
        asm volatile("cp.async.wait_group 0;");
        __syncthreads();

        if (t + 1 < TT) {
            const int nb = (t + 1) & 1;
#pragma unroll
            for (int i = 0; i < 8; i++) {
                int id = tid + i * 256;
                int r = id >> 4, c = (id & 15) * 8;
                uint32_t so = (uint32_t)(r * FSTR + c) * 2;
                long long g = (long long)(b * SS + (t + 1) * TK + r) * KVLD + c;
                cpa16(sK[nb] + so, KV_ + g);
                cpa16(sV[nb] + so, KV_ + g + 128);
            }
            asm volatile("cp.async.commit_group;");
        }

        const uint32_t sKh = sK[t & 1];
        const uint32_t sVh = sV[t & 1];

        // ---- S = Q K^T (log2 domain) ----
        float sacc[16][4] = {};
#pragma unroll
        for (int kk = 0; kk < 8; kk++) {
#pragma unroll
            for (int j = 0; j < 8; j++) {
                uint32_t boff = (uint32_t)((j*16 + ((lane >> 4) << 3) + (lane & 7)) * FSTR
                                           + kk*16 + (((lane >> 3) & 1) << 3)) * 2;
                uint32_t kh4[4];
                ldm4(kh4, sKh + boff);
                mma16(sacc[2*j],   qhr[kk], kh4);     mma16(sacc[2*j],   qlr[kk], kh4);
                mma16(sacc[2*j+1], qhr[kk], kh4 + 2); mma16(sacc[2*j+1], qlr[kk], kh4 + 2);
            }
        }

        // ---- row max + rescale ----
        float tm0 = -1e30f, tm1 = -1e30f;
#pragma unroll
        for (int ni = 0; ni < 16; ni++) {
            tm0 = fmaxf(tm0, fmaxf(sacc[ni][0], sacc[ni][1]));
            tm1 = fmaxf(tm1, fmaxf(sacc[ni][2], sacc[ni][3]));
        }
        tm0 = fmaxf(tm0, __shfl_xor_sync(0xffffffffu, tm0, 1));
        tm0 = fmaxf(tm0, __shfl_xor_sync(0xffffffffu, tm0, 2));
        tm1 = fmaxf(tm1, __shfl_xor_sync(0xffffffffu, tm1, 1));
        tm1 = fmaxf(tm1, __shfl_xor_sync(0xffffffffu, tm1, 2));
        const float mn0 = fmaxf(mrow[0], tm0), mn1 = fmaxf(mrow[1], tm1);
        const float f0 = exp2f(mrow[0] - mn0), f1 = exp2f(mrow[1] - mn1);
        mrow[0] = mn0; mrow[1] = mn1;
#pragma unroll
        for (int nd = 0; nd < 16; nd++) {
            oacc[nd][0] *= f0; oacc[nd][1] *= f0;
            oacc[nd][2] *= f1; oacc[nd][3] *= f1;
        }

        // ---- PV: unsplit P, exp/pack interleaved ----
        float rs0 = 0.f, rs1 = 0.f;
#pragma unroll
        for (int c = 0; c < 8; c++) {
            float e00 = exp2f(sacc[2*c][0]   - mn0);
            float e01 = exp2f(sacc[2*c][1]   - mn0);
            float e02 = exp2f(sacc[2*c][2]   - mn1);
            float e03 = exp2f(sacc[2*c][3]   - mn1);
            float e10 = exp2f(sacc[2*c+1][0] - mn0);
            float e11 = exp2f(sacc[2*c+1][1] - mn0);
            float e12 = exp2f(sacc[2*c+1][2] - mn1);
            float e13 = exp2f(sacc[2*c+1][3] - mn1);
            rs0 += (e00 + e01) + (e10 + e11);
            rs1 += (e02 + e03) + (e12 + e13);
            uint32_t ph4[4];
            ph4[0] = pack2(e00, e01);
            ph4[1] = pack2(e02, e03);
            ph4[2] = pack2(e10, e11);
            ph4[3] = pack2(e12, e13);
#pragma unroll
            for (int j = 0; j < 8; j++) {
                uint32_t boff = (uint32_t)((c*16 + (((lane >> 3) & 1) << 3) + (lane & 7)) * FSTR
                                           + j*16 + ((lane >> 4) << 3)) * 2;
                uint32_t vh4[4];
                ldm4t(vh4, sVh + boff);
                mma16(oacc[2*j],   ph4, vh4);
                mma16(oacc[2*j+1], ph4, vh4 + 2);
            }
        }
        rs0 += __shfl_xor_sync(0xffffffffu, rs0, 1);
        rs0 += __shfl_xor_sync(0xffffffffu, rs0, 2);
        rs1 += __shfl_xor_sync(0xffffffffu, rs1, 1);
        rs1 += __shfl_xor_sync(0xffffffffu, rs1, 2);
        lrow[0] = lrow[0] * f0 + rs0;
        lrow[1] = lrow[1] * f1 + rs1;
    }

    // ---- epilogue: O /= l, single fp16 write ----
    const float i0 = 1.f / lrow[0], i1 = 1.f / lrow[1];
    const long long orow0 = (long long)(b * SS + q0 + warp*16 + lr) * HIDDEN + h * DD;
    const long long orow1 = orow0 + 8LL * HIDDEN;
#pragma unroll
    for (int nd = 0; nd < 16; nd++) {
        const int col = nd * 8 + 2 * lc;
        *(uint32_t*)(O_ + orow0 + col) = pack2(oacc[nd][0] * i0, oacc[nd][1] * i0);
        *(uint32_t*)(O_ + orow1 + col) = pack2(oacc[nd][2] * i1, oacc[nd][3] * i1);
    }
}

// ---------------------------------------------------------------------------

extern "C" void kernel_launch(void* const* d_in, const int* in_sizes, int n_in,
                              void* d_out, int out_size) {
    const float* x  = (const float*)d_in[0];
    const float* qw = (const float*)d_in[1];
    const float* kw = (const float*)d_in[2];
    const float* vw = (const float*)d_in[3];
    const float* ow = (const float*)d_in[4];
    float* out = (float*)d_out;

    __half *xh,*xl,*w,*owp,*qh,*ql,*kv,*at;
    cudaGetSymbolAddress((void**)&xh,  g_xh);  cudaGetSymbolAddress((void**)&xl,  g_xl);
    cudaGetSymbolAddress((void**)&w,   g_w);   cudaGetSymbolAddress((void**)&owp, g_ow);
    cudaGetSymbolAddress((void**)&qh,  g_qh);  cudaGetSymbolAddress((void**)&ql,  g_ql);
    cudaGetSymbolAddress((void**)&kv,  g_kv);  cudaGetSymbolAddress((void**)&at,  g_at);

    const int SMEM0 = 3 * (3 * ASZ * 2);
    const int SMEM1 = 3 * (2 * ASZ * 2);
    cudaFuncSetAttribute((const void*)gemm_f16<0>,
                         cudaFuncAttributeMaxDynamicSharedMemorySize, SMEM0);
    cudaFuncSetAttribute((const void*)gemm_f16<1>,
                         cudaFuncAttributeMaxDynamicSharedMemorySize, SMEM1);
    cudaFuncSetAttribute((const void*)flash_attn,
                         cudaFuncAttributeMaxDynamicSharedMemorySize, FSMEM);

    // 0) fused prep
    prep<<<PREP_X_BLKS + PREP_W_BLKS + PREP_OW_BLKS, 256>>>(
        x, qw, kw, vw, ow, xh, xl, w, owp);

    // 1) fused QKV projection
    gemm_f16<0><<<dim3(NQKV/BN, (BB*SS)/BM), 256, SMEM0>>>(
        xh, xl, w, qh, ql, kv, nullptr);

    // 2) fused attention (P unsplit)
    flash_attn<<<dim3(SS/TQ, BB*HEADS), 256, FSMEM>>>(qh, ql, kv, at);

    // 3) out = attn @ Ow^T
    gemm_f16<1><<<dim3(HIDDEN/BN, (BB*SS)/BM), 256, SMEM1>>>(
        at, nullptr, owp, nullptr, nullptr, nullptr, out);
}

// round 12
// speedup vs baseline: 1.4637x; 1.1645x over previous
#include <cuda_runtime.h>
#include <cuda_fp16.h>
#include <cstdint>

// ---------------------------------------------------------------------------
// ProductionFastMQA round 12:
//   * QKV projection: UNSPLIT x operand (1 MMA per k16, was 2) — x rounded
//     to fp16 once; Q still emitted as hi/lo pair from the fp32 accumulator.
//   * flash / O-proj unchanged from round 11.
// ---------------------------------------------------------------------------

#define HIDDEN   2048
#define HEADS    16
#define HEAD_DIM 128
#define BB       2
#define SS       2048
#define SCALE    0.08838834764831845f
#define LOG2E    1.4426950408889634f
#define QSCALE   (SCALE * LOG2E)
#define NQKV     2304
#define KVLD     256

// gemm tiles
#define BM   128
#define BN   128
#define BKb  32
#define ASTR (BKb + 8)            // 40 halves
#define ASZ  (BM * ASTR)          // 5120 halves
#define GST  (2 * ASZ * 2)        // A + B planes per stage = 20480 B
#define SMEMG (3 * GST)           // 61440 B, 3-stage ring

// flash tiles
#define TQ 128
#define TK 128
#define DD 128
#define FSTR 136
#define FTB  (TQ * FSTR * 2)
#define FSMEM (4 * FTB)           // K0 K1 V0 V1

// prep grid regions (256 threads, 4 floats each)
#define PREP_X_BLKS   8192
#define PREP_W_BLKS   4608
#define PREP_OW_BLKS  4096

// ----------------------------- scratch -------------------------------------
__device__ __half g_x[BB*SS*HIDDEN];           // x, single fp16
__device__ __half g_w[NQKV*HIDDEN];
__device__ __half g_ow[HIDDEN*HIDDEN];
__device__ __half g_qh[BB*SS*HIDDEN],  g_ql[BB*SS*HIDDEN];
__device__ __half g_kv[BB*SS*KVLD];
__device__ __half g_at[BB*SS*HIDDEN];

// ----------------------------- PTX helpers ---------------------------------
__device__ __forceinline__ uint32_t smem_u32(const void* p) {
    uint32_t a;
    asm("{ .reg .u64 t; cvta.to.shared.u64 t, %1; cvt.u32.u64 %0, t; }"
        : "=r"(a) : "l"(p));
    return a;
}
__device__ __forceinline__ void ldm4(uint32_t* r, uint32_t a) {
    asm volatile("ldmatrix.sync.aligned.m8n8.x4.shared.b16 {%0,%1,%2,%3},[%4];"
                 : "=r"(r[0]), "=r"(r[1]), "=r"(r[2]), "=r"(r[3]) : "r"(a));
}
__device__ __forceinline__ void ldm4t(uint32_t* r, uint32_t a) {
    asm volatile("ldmatrix.sync.aligned.m8n8.x4.trans.shared.b16 {%0,%1,%2,%3},[%4];"
                 : "=r"(r[0]), "=r"(r[1]), "=r"(r[2]), "=r"(r[3]) : "r"(a));
}
__device__ __forceinline__ void cpa16(uint32_t d, const void* s) {
    asm volatile("cp.async.cg.shared.global [%0],[%1],16;" :: "r"(d), "l"(s));
}
__device__ __forceinline__ void mma16(float* c, const uint32_t* a, const uint32_t* b) {
    asm volatile(
        "mma.sync.aligned.m16n8k16.row.col.f32.f16.f16.f32 "
        "{%0,%1,%2,%3},{%4,%5,%6,%7},{%8,%9},{%0,%1,%2,%3};"
        : "+f"(c[0]), "+f"(c[1]), "+f"(c[2]), "+f"(c[3])
        : "r"(a[0]), "r"(a[1]), "r"(a[2]), "r"(a[3]), "r"(b[0]), "r"(b[1]));
}
__device__ __forceinline__ void packpair(float a, float b, uint32_t& hi, uint32_t& lo) {
    __half2 H = __floats2half2_rn(a, b);
    float2 F = __half22float2(H);
    __half2 L = __floats2half2_rn(a - F.x, b - F.y);
    hi = *reinterpret_cast<const uint32_t*>(&H);
    lo = *reinterpret_cast<const uint32_t*>(&L);
}
__device__ __forceinline__ uint32_t pack2(float a, float b) {
    __half2 H = __floats2half2_rn(a, b);
    return *reinterpret_cast<const uint32_t*>(&H);
}

// ---------------------------------------------------------------------------
// fp16 GEMM, single A plane (1 MMA/k16), 3-stage ring.
// C = A[M,2048] @ (B[N,2048])^T
// MODE 0: QKV — Q cols -> hi/lo pair, KV cols -> single fp16.
// MODE 1: fp32 output ldc=2048.
// ---------------------------------------------------------------------------
template <int MODE>
__global__ __launch_bounds__(256, 2) void gemm_f16(
    const __half* __restrict__ Ah, const __half* __restrict__ Bh,
    __half* __restrict__ Qhi, __half* __restrict__ Qlo,
    __half* __restrict__ KVo, float* __restrict__ Cf)
{
    extern __shared__ __half sm[];
    const uint32_t sb = smem_u32(sm);

    const int tid = threadIdx.x, lane = tid & 31, warp = tid >> 5;
    const int wm0 = (warp >> 2) * 64;
    const int wn0 = (warp & 3) * 32;
    const int m0 = blockIdx.y * BM, n0 = blockIdx.x * BN;

    float acc[4][4][4] = {};
    const int ar = tid >> 2;
    const int ac = (tid & 3) * 8;

    auto ld_stage = [&](int kt, int s) {
        const uint32_t st = sb + (uint32_t)s * GST;
#pragma unroll
        for (int i = 0; i < 2; i++) {
            int r = ar + i * 64;
            long long go = (long long)(m0 + r) * HIDDEN + kt + ac;
            uint32_t so = (uint32_t)(r * ASTR + ac) * 2;
            cpa16(st + so, Ah + go);
            long long gb = (long long)(n0 + r) * HIDDEN + kt + ac;
            cpa16(st + ASZ*2 + so, Bh + gb);
        }
    };

    const int T = HIDDEN / BKb;
    ld_stage(0, 0);
    asm volatile("cp.async.commit_group;");
    ld_stage(BKb, 1);
    asm volatile("cp.async.commit_group;");

    for (int t = 0; t < T; t++) {
        if (t + 1 < T) {
            asm volatile("cp.async.wait_group 1;");
        } else {
            asm volatile("cp.async.wait_group 0;");
        }
        __syncthreads();
        if (t + 2 < T) {
            ld_stage((t + 2) * BKb, (t + 2) % 3);
            asm volatile("cp.async.commit_group;");
        }

        const uint32_t st = sb + (uint32_t)(t % 3) * GST;
        const uint32_t aH0 = st;
        const uint32_t bH0 = st + ASZ*2;

#pragma unroll
        for (int kk = 0; kk < BKb; kk += 16) {
            uint32_t ah[4][4];
            const int arow = wm0 + (lane & 15);
            const int acol = kk + ((lane >> 4) << 3);
#pragma unroll
            for (int mi = 0; mi < 4; mi++) {
                uint32_t off = (uint32_t)((arow + mi*16) * ASTR + acol) * 2;
                ldm4(ah[mi], aH0 + off);
            }
            uint32_t bh[4][2];
            const int br = wn0 + ((lane >> 4) << 3) + (lane & 7);
            const int bc = kk + (((lane >> 3) & 1) << 3);
#pragma unroll
            for (int j = 0; j < 2; j++) {
                uint32_t off = (uint32_t)((br + j*16) * ASTR + bc) * 2;
                uint32_t r4[4];
                ldm4(r4, bH0 + off);
                bh[2*j][0]=r4[0]; bh[2*j][1]=r4[1]; bh[2*j+1][0]=r4[2]; bh[2*j+1][1]=r4[3];
            }
#pragma unroll
            for (int mi = 0; mi < 4; mi++)
#pragma unroll
                for (int ni = 0; ni < 4; ni++)
                    mma16(acc[mi][ni], ah[mi], bh[ni]);
        }
    }

    const int lr = lane >> 2, lc = lane & 3;
    if (MODE == 0) {
        const bool isQ = (n0 < HIDDEN);
        if (isQ) {
#pragma unroll
            for (int mi = 0; mi < 4; mi++)
#pragma unroll
                for (int ni = 0; ni < 4; ni++) {
                    const int row = m0 + wm0 + mi*16 + lr;
                    const int col = n0 + wn0 + ni*8 + 2*lc;
#pragma unroll
                    for (int hf = 0; hf < 2; hf++) {
                        uint32_t hh, ll;
                        packpair(acc[mi][ni][2*hf], acc[mi][ni][2*hf + 1], hh, ll);
                        long long o = (long long)(row + 8*hf) * HIDDEN + col;
                        *(uint32_t*)(Qhi + o) = hh;
                        *(uint32_t*)(Qlo + o) = ll;
                    }
                }
        } else {
            const int cb = n0 - HIDDEN;
#pragma unroll
            for (int mi = 0; mi < 4; mi++)
#pragma unroll
                for (int ni = 0; ni < 4; ni++) {
                    const int row = m0 + wm0 + mi*16 + lr;
                    const int col = cb + wn0 + ni*8 + 2*lc;
#pragma unroll
                    for (int hf = 0; hf < 2; hf++) {
                        long long o = (long long)(row + 8*hf) * KVLD + col;
                        *(uint32_t*)(KVo + o) =
                            pack2(acc[mi][ni][2*hf], acc[mi][ni][2*hf + 1]);
                    }
                }
        }
    } else {
#pragma unroll
        for (int mi = 0; mi < 4; mi++)
#pragma unroll
            for (int ni = 0; ni < 4; ni++) {
                const int row = m0 + wm0 + mi*16 + lr;
                const int col = n0 + wn0 + ni*8 + 2*lc;
                long long o = (long long)row * HIDDEN + col;
                *(float2*)(Cf + o) = make_float2(acc[mi][ni][0], acc[mi][ni][1]);
                *(float2*)(Cf + o + 8LL * HIDDEN) =
                    make_float2(acc[mi][ni][2], acc[mi][ni][3]);
            }
    }
}

// ------------------------- fused prep kernel --------------------------------
__global__ __launch_bounds__(256) void prep(
    const float* __restrict__ x,  const float* __restrict__ qw,
    const float* __restrict__ kw, const float* __restrict__ vw,
    const float* __restrict__ ow,
    __half* __restrict__ xo, __half* __restrict__ w, __half* __restrict__ owp)
{
    const int bid = blockIdx.x;
    if (bid < PREP_X_BLKS) {
        int i = bid * 256 + threadIdx.x;
        float4 v = ((const float4*)x)[i];
        ((uint32_t*)xo)[2*i]     = pack2(v.x, v.y);
        ((uint32_t*)xo)[2*i + 1] = pack2(v.z, v.w);
    } else if (bid < PREP_X_BLKS + PREP_W_BLKS) {
        int i = (bid - PREP_X_BLKS) * 256 + threadIdx.x;
        long long e = (long long)i * 4;
        int r = (int)(e >> 11);
        int c = (int)(e & 2047);
        const float* src;
        float sc = 1.0f;
        if (r < 2048)      { src = qw + ((long long)r << 11) + c; sc = QSCALE; }
        else if (r < 2176) { src = kw + ((long long)(r - 2048) << 11) + c; }
        else               { src = vw + ((long long)(r - 2176) << 11) + c; }
        float4 v = *(const float4*)src;
        ((uint32_t*)w)[2*i]     = pack2(v.x * sc, v.y * sc);
        ((uint32_t*)w)[2*i + 1] = pack2(v.z * sc, v.w * sc);
    } else {
        int i = (bid - PREP_X_BLKS - PREP_W_BLKS) * 256 + threadIdx.x;
        float4 v = ((const float4*)ow)[i];
        ((uint32_t*)owp)[2*i]     = pack2(v.x, v.y);
        ((uint32_t*)owp)[2*i + 1] = pack2(v.z, v.w);
    }
}

// ---------------------------------------------------------------------------
// Flash attention (round 11, unchanged): Q split in S, P unsplit in PV.
// ---------------------------------------------------------------------------
__global__ __launch_bounds__(256, 1) void flash_attn(
    const __half* __restrict__ Qh_, const __half* __restrict__ Ql_,
    const __half* __restrict__ KV_, __half* __restrict__ O_)
{
    extern __shared__ __half fsm[];
    const int b = blockIdx.y >> 4, h = blockIdx.y & 15;
    const int q0 = blockIdx.x * TQ;
    const int tid = threadIdx.x, lane = tid & 31, warp = tid >> 5;
    const int lr = lane >> 2, lc = lane & 3;

    const uint32_t s0 = smem_u32(fsm);
    const uint32_t sK[2] = {s0, s0 + FTB};
    const uint32_t sV[2] = {s0 + 2*FTB, s0 + 3*FTB};

#pragma unroll
    for (int i = 0; i < 8; i++) {
        int id = tid + i * 256;
        int r = id >> 4, c = (id & 15) * 8;
        uint32_t so = (uint32_t)(r * FSTR + c) * 2;
        long long gq = (long long)(b * SS + q0 + r) * HIDDEN + h * DD + c;
        cpa16(sK[0] + so, Qh_ + gq);
        cpa16(sK[1] + so, Ql_ + gq);
    }
    asm volatile("cp.async.commit_group;");
    asm volatile("cp.async.wait_group 0;");
    __syncthreads();

    uint32_t qhr[8][4], qlr[8][4];
#pragma unroll
    for (int kk = 0; kk < 8; kk++) {
        uint32_t aoff = (uint32_t)((warp*16 + (lane & 15)) * FSTR
                                   + kk*16 + ((lane >> 4) << 3)) * 2;
        ldm4(qhr[kk], sK[0] + aoff);
        ldm4(qlr[kk], sK[1] + aoff);
    }
    __syncthreads();

#pragma unroll
    for (int i = 0; i < 8; i++) {
        int id = tid + i * 256;
        int r = id >> 4, c = (id & 15) * 8;
        uint32_t so = (uint32_t)(r * FSTR + c) * 2;
        long long g = (long long)(b * SS + r) * KVLD + c;
        cpa16(sK[0] + so, KV_ + g);
        cpa16(sV[0] + so, KV_ + g + 128);
    }
    asm volatile("cp.async.commit_group;");

    float oacc[16][4] = {};
    float mrow[2] = {-1e30f, -1e30f};
    float lrow[2] = {0.f, 0.f};

    const int TT = SS / TK;
    for (int t = 0; t < TT; t++) {
        asm volatile("cp.async.wait_group 0;");
        __syncthreads();

        if (t + 1 < TT) {
            const int nb = (t + 1) & 1;
#pragma unroll
            for (int i = 0; i < 8; i++) {
                int id = tid + i * 256;
                int r = id >> 4, c = (id & 15) * 8;
                uint32_t so = (uint32_t)(r * FSTR + c) * 2;
                long long g = (long long)(b * SS + (t + 1) * TK + r) * KVLD + c;
                cpa16(sK[nb] + so, KV_ + g);
                cpa16(sV[nb] + so, KV_ + g + 128);
            }
            asm volatile("cp.async.commit_group;");
        }

        const uint32_t sKh = sK[t & 1];
        const uint32_t sVh = sV[t & 1];

        float sacc[16][4] = {};
#pragma unroll
        for (int kk = 0; kk < 8; kk++) {
#pragma unroll
            for (int j = 0; j < 8; j++) {
                uint32_t boff = (uint32_t)((j*16 + ((lane >> 4) << 3) + (lane & 7)) * FSTR
                                           + kk*16 + (((lane >> 3) & 1) << 3)) * 2;
                uint32_t kh4[4];
                ldm4(kh4, sKh + boff);
                mma16(sacc[2*j],   qhr[kk], kh4);     mma16(sacc[2*j],   qlr[kk], kh4);
                mma16(sacc[2*j+1], qhr[kk], kh4 + 2); mma16(sacc[2*j+1], qlr[kk], kh4 + 2);
            }
        }

        float tm0 = -1e30f, tm1 = -1e30f;
#pragma unroll
        for (int ni = 0; ni < 16; ni++) {
            tm0 = fmaxf(tm0, fmaxf(sacc[ni][0], sacc[ni][1]));
            tm1 = fmaxf(tm1, fmaxf(sacc[ni][2], sacc[ni][3]));
        }
        tm0 = fmaxf(tm0, __shfl_xor_sync(0xffffffffu, tm0, 1));
        tm0 = fmaxf(tm0, __shfl_xor_sync(0xffffffffu, tm0, 2));
        tm1 = fmaxf(tm1, __shfl_xor_sync(0xffffffffu, tm1, 1));
        tm1 = fmaxf(tm1, __shfl_xor_sync(0xffffffffu, tm1, 2));
        const float mn0 = fmaxf(mrow[0], tm0), mn1 = fmaxf(mrow[1], tm1);
        const float f0 = exp2f(mrow[0] - mn0), f1 = exp2f(mrow[1] - mn1);
        mrow[0] = mn0; mrow[1] = mn1;
#pragma unroll
        for (int nd = 0; nd < 16; nd++) {
            oacc[nd][0] *= f0; oacc[nd][1] *= f0;
            oacc[nd][2] *= f1; oacc[nd][3] *= f1;
        }

        float rs0 = 0.f, rs1 = 0.f;
#pragma unroll
        for (int c = 0; c < 8; c++) {
            float e00 = exp2f(sacc[2*c][0]   - mn0);
            float e01 = exp2f(sacc[2*c][1]   - mn0);
            float e02 = exp2f(sacc[2*c][2]   - mn1);
            float e03 = exp2f(sacc[2*c][3]   - mn1);
            float e10 = exp2f(sacc[2*c+1][0] - mn0);
            float e11 = exp2f(sacc[2*c+1][1] - mn0);
            float e12 = exp2f(sacc[2*c+1][2] - mn1);
            float e13 = exp2f(sacc[2*c+1][3] - mn1);
            rs0 += (e00 + e01) + (e10 + e11);
            rs1 += (e02 + e03) + (e12 + e13);
            uint32_t ph4[4];
            ph4[0] = pack2(e00, e01);
            ph4[1] = pack2(e02, e03);
            ph4[2] = pack2(e10, e11);
            ph4[3] = pack2(e12, e13);
#pragma unroll
            for (int j = 0; j < 8; j++) {
                uint32_t boff = (uint32_t)((c*16 + (((lane >> 3) & 1) << 3) + (lane & 7)) * FSTR
                                           + j*16 + ((lane >> 4) << 3)) * 2;
                uint32_t vh4[4];
                ldm4t(vh4, sVh + boff);
                mma16(oacc[2*j],   ph4, vh4);
                mma16(oacc[2*j+1], ph4, vh4 + 2);
            }
        }
        rs0 += __shfl_xor_sync(0xffffffffu, rs0, 1);
        rs0 += __shfl_xor_sync(0xffffffffu, rs0, 2);
        rs1 += __shfl_xor_sync(0xffffffffu, rs1, 1);
        rs1 += __shfl_xor_sync(0xffffffffu, rs1, 2);
        lrow[0] = lrow[0] * f0 + rs0;
        lrow[1] = lrow[1] * f1 + rs1;
    }

    const float i0 = 1.f / lrow[0], i1 = 1.f / lrow[1];
    const long long orow0 = (long long)(b * SS + q0 + warp*16 + lr) * HIDDEN + h * DD;
    const long long orow1 = orow0 + 8LL * HIDDEN;
#pragma unroll
    for (int nd = 0; nd < 16; nd++) {
        const int col = nd * 8 + 2 * lc;
        *(uint32_t*)(O_ + orow0 + col) = pack2(oacc[nd][0] * i0, oacc[nd][1] * i0);
        *(uint32_t*)(O_ + orow1 + col) = pack2(oacc[nd][2] * i1, oacc[nd][3] * i1);
    }
}

// ---------------------------------------------------------------------------

extern "C" void kernel_launch(void* const* d_in, const int* in_sizes, int n_in,
                              void* d_out, int out_size) {
    const float* x  = (const float*)d_in[0];
    const float* qw = (const float*)d_in[1];
    const float* kw = (const float*)d_in[2];
    const float* vw = (const float*)d_in[3];
    const float* ow = (const float*)d_in[4];
    float* out = (float*)d_out;

    __half *xp,*w,*owp,*qh,*ql,*kv,*at;
    cudaGetSymbolAddress((void**)&xp,  g_x);
    cudaGetSymbolAddress((void**)&w,   g_w);   cudaGetSymbolAddress((void**)&owp, g_ow);
    cudaGetSymbolAddress((void**)&qh,  g_qh);  cudaGetSymbolAddress((void**)&ql,  g_ql);
    cudaGetSymbolAddress((void**)&kv,  g_kv);  cudaGetSymbolAddress((void**)&at,  g_at);

    cudaFuncSetAttribute((const void*)gemm_f16<0>,
                         cudaFuncAttributeMaxDynamicSharedMemorySize, SMEMG);
    cudaFuncSetAttribute((const void*)gemm_f16<1>,
                         cudaFuncAttributeMaxDynamicSharedMemorySize, SMEMG);
    cudaFuncSetAttribute((const void*)flash_attn,
                         cudaFuncAttributeMaxDynamicSharedMemorySize, FSMEM);

    // 0) fused prep
    prep<<<PREP_X_BLKS + PREP_W_BLKS + PREP_OW_BLKS, 256>>>(
        x, qw, kw, vw, ow, xp, w, owp);

    // 1) fused QKV projection (single-A fp16, 1 MMA/k16)
    gemm_f16<0><<<dim3(NQKV/BN, (BB*SS)/BM), 256, SMEMG>>>(
        xp, w, qh, ql, kv, nullptr);

    // 2) fused attention (Q split, P unsplit)
    flash_attn<<<dim3(SS/TQ, BB*HEADS), 256, FSMEM>>>(qh, ql, kv, at);

    // 3) out = attn @ Ow^T
    gemm_f16<1><<<dim3(HIDDEN/BN, (BB*SS)/BM), 256, SMEMG>>>(
        at, owp, nullptr, nullptr, nullptr, out);
}

// round 13
// speedup vs baseline: 1.6593x; 1.1336x over previous
#include <cuda_runtime.h>
#include <cuda_fp16.h>
#include <cstdint>

// ---------------------------------------------------------------------------
// ProductionFastMQA round 13:
//   * flash S-stage: UNSPLIT Q operand (1 MMA per k16, was 2) — K was already
//     unsplit; softmax normalization cancels common-mode exponent error.
//   * QKV epilogue writes single-plane fp16 Q (g_ql removed).
//   * O-proj / prep unchanged.
// Every GEMM stage now runs at 1 MMA per k16 — fp16-minimal instruction count.
// ---------------------------------------------------------------------------

#define HIDDEN   2048
#define HEADS    16
#define HEAD_DIM 128
#define BB       2
#define SS       2048
#define SCALE    0.08838834764831845f
#define LOG2E    1.4426950408889634f
#define QSCALE   (SCALE * LOG2E)
#define NQKV     2304
#define KVLD     256

// gemm tiles
#define BM   128
#define BN   128
#define BKb  32
#define ASTR (BKb + 8)            // 40 halves
#define ASZ  (BM * ASTR)          // 5120 halves
#define GST  (2 * ASZ * 2)        // A + B planes per stage = 20480 B
#define SMEMG (3 * GST)           // 61440 B, 3-stage ring

// flash tiles
#define TQ 128
#define TK 128
#define DD 128
#define FSTR 136
#define FTB  (TQ * FSTR * 2)
#define FSMEM (4 * FTB)           // K0 K1 V0 V1

// prep grid regions (256 threads, 4 floats each)
#define PREP_X_BLKS   8192
#define PREP_W_BLKS   4608
#define PREP_OW_BLKS  4096

// ----------------------------- scratch -------------------------------------
__device__ __half g_x[BB*SS*HIDDEN];
__device__ __half g_w[NQKV*HIDDEN];
__device__ __half g_ow[HIDDEN*HIDDEN];
__device__ __half g_q[BB*SS*HIDDEN];           // Q, single fp16
__device__ __half g_kv[BB*SS*KVLD];
__device__ __half g_at[BB*SS*HIDDEN];

// ----------------------------- PTX helpers ---------------------------------
__device__ __forceinline__ uint32_t smem_u32(const void* p) {
    uint32_t a;
    asm("{ .reg .u64 t; cvta.to.shared.u64 t, %1; cvt.u32.u64 %0, t; }"
        : "=r"(a) : "l"(p));
    return a;
}
__device__ __forceinline__ void ldm4(uint32_t* r, uint32_t a) {
    asm volatile("ldmatrix.sync.aligned.m8n8.x4.shared.b16 {%0,%1,%2,%3},[%4];"
                 : "=r"(r[0]), "=r"(r[1]), "=r"(r[2]), "=r"(r[3]) : "r"(a));
}
__device__ __forceinline__ void ldm4t(uint32_t* r, uint32_t a) {
    asm volatile("ldmatrix.sync.aligned.m8n8.x4.trans.shared.b16 {%0,%1,%2,%3},[%4];"
                 : "=r"(r[0]), "=r"(r[1]), "=r"(r[2]), "=r"(r[3]) : "r"(a));
}
__device__ __forceinline__ void cpa16(uint32_t d, const void* s) {
    asm volatile("cp.async.cg.shared.global [%0],[%1],16;" :: "r"(d), "l"(s));
}
__device__ __forceinline__ void mma16(float* c, const uint32_t* a, const uint32_t* b) {
    asm volatile(
        "mma.sync.aligned.m16n8k16.row.col.f32.f16.f16.f32 "
        "{%0,%1,%2,%3},{%4,%5,%6,%7},{%8,%9},{%0,%1,%2,%3};"
        : "+f"(c[0]), "+f"(c[1]), "+f"(c[2]), "+f"(c[3])
        : "r"(a[0]), "r"(a[1]), "r"(a[2]), "r"(a[3]), "r"(b[0]), "r"(b[1]));
}
__device__ __forceinline__ uint32_t pack2(float a, float b) {
    __half2 H = __floats2half2_rn(a, b);
    return *reinterpret_cast<const uint32_t*>(&H);
}

// ---------------------------------------------------------------------------
// fp16 GEMM, single A plane (1 MMA/k16), 3-stage ring.
// C = A[M,2048] @ (B[N,2048])^T
// MODE 0: QKV — Q cols and KV cols both single fp16 (routed).
// MODE 1: fp32 output ldc=2048.
// ---------------------------------------------------------------------------
template <int MODE>
__global__ __launch_bounds__(256, 2) void gemm_f16(
    const __half* __restrict__ Ah, const __half* __restrict__ Bh,
    __half* __restrict__ Qo, __half* __restrict__ KVo, float* __restrict__ Cf)
{
    extern __shared__ __half sm[];
    const uint32_t sb = smem_u32(sm);

    const int tid = threadIdx.x, lane = tid & 31, warp = tid >> 5;
    const int wm0 = (warp >> 2) * 64;
    const int wn0 = (warp & 3) * 32;
    const int m0 = blockIdx.y * BM, n0 = blockIdx.x * BN;

    float acc[4][4][4] = {};
    const int ar = tid >> 2;
    const int ac = (tid & 3) * 8;

    auto ld_stage = [&](int kt, int s) {
        const uint32_t st = sb + (uint32_t)s * GST;
#pragma unroll
        for (int i = 0; i < 2; i++) {
            int r = ar + i * 64;
            long long go = (long long)(m0 + r) * HIDDEN + kt + ac;
            uint32_t so = (uint32_t)(r * ASTR + ac) * 2;
            cpa16(st + so, Ah + go);
            long long gb = (long long)(n0 + r) * HIDDEN + kt + ac;
            cpa16(st + ASZ*2 + so, Bh + gb);
        }
    };

    const int T = HIDDEN / BKb;
    ld_stage(0, 0);
    asm volatile("cp.async.commit_group;");
    ld_stage(BKb, 1);
    asm volatile("cp.async.commit_group;");

    for (int t = 0; t < T; t++) {
        if (t + 1 < T) {
            asm volatile("cp.async.wait_group 1;");
        } else {
            asm volatile("cp.async.wait_group 0;");
        }
        __syncthreads();
        if (t + 2 < T) {
            ld_stage((t + 2) * BKb, (t + 2) % 3);
            asm volatile("cp.async.commit_group;");
        }

        const uint32_t st = sb + (uint32_t)(t % 3) * GST;
        const uint32_t aH0 = st;
        const uint32_t bH0 = st + ASZ*2;

#pragma unroll
        for (int kk = 0; kk < BKb; kk += 16) {
            uint32_t ah[4][4];
            const int arow = wm0 + (lane & 15);
            const int acol = kk + ((lane >> 4) << 3);
#pragma unroll
            for (int mi = 0; mi < 4; mi++) {
                uint32_t off = (uint32_t)((arow + mi*16) * ASTR + acol) * 2;
                ldm4(ah[mi], aH0 + off);
            }
            uint32_t bh[4][2];
            const int br = wn0 + ((lane >> 4) << 3) + (lane & 7);
            const int bc = kk + (((lane >> 3) & 1) << 3);
#pragma unroll
            for (int j = 0; j < 2; j++) {
                uint32_t off = (uint32_t)((br + j*16) * ASTR + bc) * 2;
                uint32_t r4[4];
                ldm4(r4, bH0 + off);
                bh[2*j][0]=r4[0]; bh[2*j][1]=r4[1]; bh[2*j+1][0]=r4[2]; bh[2*j+1][1]=r4[3];
            }
#pragma unroll
            for (int mi = 0; mi < 4; mi++)
#pragma unroll
                for (int ni = 0; ni < 4; ni++)
                    mma16(acc[mi][ni], ah[mi], bh[ni]);
        }
    }

    const int lr = lane >> 2, lc = lane & 3;
    if (MODE == 0) {
        const bool isQ = (n0 < HIDDEN);
        __half* Op = isQ ? Qo : KVo;
        const int ldc = isQ ? HIDDEN : KVLD;
        const int cb  = isQ ? n0 : (n0 - HIDDEN);
#pragma unroll
        for (int mi = 0; mi < 4; mi++)
#pragma unroll
            for (int ni = 0; ni < 4; ni++) {
                const int row = m0 + wm0 + mi*16 + lr;
                const int col = cb + wn0 + ni*8 + 2*lc;
#pragma unroll
                for (int hf = 0; hf < 2; hf++) {
                    long long o = (long long)(row + 8*hf) * ldc + col;
                    *(uint32_t*)(Op + o) =
                        pack2(acc[mi][ni][2*hf], acc[mi][ni][2*hf + 1]);
                }
            }
    } else {
#pragma unroll
        for (int mi = 0; mi < 4; mi++)
#pragma unroll
            for (int ni = 0; ni < 4; ni++) {
                const int row = m0 + wm0 + mi*16 + lr;
                const int col = n0 + wn0 + ni*8 + 2*lc;
                long long o = (long long)row * HIDDEN + col;
                *(float2*)(Cf + o) = make_float2(acc[mi][ni][0], acc[mi][ni][1]);
                *(float2*)(Cf + o + 8LL * HIDDEN) =
                    make_float2(acc[mi][ni][2], acc[mi][ni][3]);
            }
    }
}

// ------------------------- fused prep kernel --------------------------------
__global__ __launch_bounds__(256) void prep(
    const float* __restrict__ x,  const float* __restrict__ qw,
    const float* __restrict__ kw, const float* __restrict__ vw,
    const float* __restrict__ ow,
    __half* __restrict__ xo, __half* __restrict__ w, __half* __restrict__ owp)
{
    const int bid = blockIdx.x;
    if (bid < PREP_X_BLKS) {
        int i = bid * 256 + threadIdx.x;
        float4 v = ((const float4*)x)[i];
        ((uint32_t*)xo)[2*i]     = pack2(v.x, v.y);
        ((uint32_t*)xo)[2*i + 1] = pack2(v.z, v.w);
    } else if (bid < PREP_X_BLKS + PREP_W_BLKS) {
        int i = (bid - PREP_X_BLKS) * 256 + threadIdx.x;
        long long e = (long long)i * 4;
        int r = (int)(e >> 11);
        int c = (int)(e & 2047);
        const float* src;
        float sc = 1.0f;
        if (r < 2048)      { src = qw + ((long long)r << 11) + c; sc = QSCALE; }
        else if (r < 2176) { src = kw + ((long long)(r - 2048) << 11) + c; }
        else               { src = vw + ((long long)(r - 2176) << 11) + c; }
        float4 v = *(const float4*)src;
        ((uint32_t*)w)[2*i]     = pack2(v.x * sc, v.y * sc);
        ((uint32_t*)w)[2*i + 1] = pack2(v.z * sc, v.w * sc);
    } else {
        int i = (bid - PREP_X_BLKS - PREP_W_BLKS) * 256 + threadIdx.x;
        float4 v = ((const float4*)ow)[i];
        ((uint32_t*)owp)[2*i]     = pack2(v.x, v.y);
        ((uint32_t*)owp)[2*i + 1] = pack2(v.z, v.w);
    }
}

// ---------------------------------------------------------------------------
// Flash attention: Q single fp16 (1 MMA/k16 in S), P unsplit (1 MMA/k16 in
// PV). K/V double-buffered, one sync per iteration.
// ---------------------------------------------------------------------------
__global__ __launch_bounds__(256, 1) void flash_attn(
    const __half* __restrict__ Q_, const __half* __restrict__ KV_,
    __half* __restrict__ O_)
{
    extern __shared__ __half fsm[];
    const int b = blockIdx.y >> 4, h = blockIdx.y & 15;
    const int q0 = blockIdx.x * TQ;
    const int tid = threadIdx.x, lane = tid & 31, warp = tid >> 5;
    const int lr = lane >> 2, lc = lane & 3;

    const uint32_t s0 = smem_u32(fsm);
    const uint32_t sK[2] = {s0, s0 + FTB};
    const uint32_t sV[2] = {s0 + 2*FTB, s0 + 3*FTB};

    // ---- stage Q (one plane), hoist to registers ----
#pragma unroll
    for (int i = 0; i < 8; i++) {
        int id = tid + i * 256;
        int r = id >> 4, c = (id & 15) * 8;
        uint32_t so = (uint32_t)(r * FSTR + c) * 2;
        long long gq = (long long)(b * SS + q0 + r) * HIDDEN + h * DD + c;
        cpa16(sK[0] + so, Q_ + gq);
    }
    asm volatile("cp.async.commit_group;");
    asm volatile("cp.async.wait_group 0;");
    __syncthreads();

    uint32_t qhr[8][4];
#pragma unroll
    for (int kk = 0; kk < 8; kk++) {
        uint32_t aoff = (uint32_t)((warp*16 + (lane & 15)) * FSTR
                                   + kk*16 + ((lane >> 4) << 3)) * 2;
        ldm4(qhr[kk], sK[0] + aoff);
    }
    __syncthreads();

    // ---- prefetch K(0)+V(0) ----
#pragma unroll
    for (int i = 0; i < 8; i++) {
        int id = tid + i * 256;
        int r = id >> 4, c = (id & 15) * 8;
        uint32_t so = (uint32_t)(r * FSTR + c) * 2;
        long long g = (long long)(b * SS + r) * KVLD + c;
        cpa16(sK[0] + so, KV_ + g);
        cpa16(sV[0] + so, KV_ + g + 128);
    }
    asm volatile("cp.async.commit_group;");

    float oacc[16][4] = {};
    float mrow[2] = {-1e30f, -1e30f};
    float lrow[2] = {0.f, 0.f};

    const int TT = SS / TK;
    for (int t = 0; t < TT; t++) {
        asm volatile("cp.async.wait_group 0;");
        __syncthreads();

        if (t + 1 < TT) {
            const int nb = (t + 1) & 1;
#pragma unroll
            for (int i = 0; i < 8; i++) {
                int id = tid + i * 256;
                int r = id >> 4, c = (id & 15) * 8;
                uint32_t so = (uint32_t)(r * FSTR + c) * 2;
                long long g = (long long)(b * SS + (t + 1) * TK + r) * KVLD + c;
                cpa16(sK[nb] + so, KV_ + g);
                cpa16(sV[nb] + so, KV_ + g + 128);
            }
            asm volatile("cp.async.commit_group;");
        }

        const uint32_t sKh = sK[t & 1];
        const uint32_t sVh = sV[t & 1];

        // ---- S = Q K^T (log2 domain, single-plane Q) ----
        float sacc[16][4] = {};
#pragma unroll
        for (int kk = 0; kk < 8; kk++) {
#pragma unroll
            for (int j = 0; j < 8; j++) {
                uint32_t boff = (uint32_t)((j*16 + ((lane >> 4) << 3) + (lane & 7)) * FSTR
                                           + kk*16 + (((lane >> 3) & 1) << 3)) * 2;
                uint32_t kh4[4];
                ldm4(kh4, sKh + boff);
                mma16(sacc[2*j],   qhr[kk], kh4);
                mma16(sacc[2*j+1], qhr[kk], kh4 + 2);
            }
        }

        // ---- row max + rescale ----
        float tm0 = -1e30f, tm1 = -1e30f;
#pragma unroll
        for (int ni = 0; ni < 16; ni++) {
            tm0 = fmaxf(tm0, fmaxf(sacc[ni][0], sacc[ni][1]));
            tm1 = fmaxf(tm1, fmaxf(sacc[ni][2], sacc[ni][3]));
        }
        tm0 = fmaxf(tm0, __shfl_xor_sync(0xffffffffu, tm0, 1));
        tm0 = fmaxf(tm0, __shfl_xor_sync(0xffffffffu, tm0, 2));
        tm1 = fmaxf(tm1, __shfl_xor_sync(0xffffffffu, tm1, 1));
        tm1 = fmaxf(tm1, __shfl_xor_sync(0xffffffffu, tm1, 2));
        const float mn0 = fmaxf(mrow[0], tm0), mn1 = fmaxf(mrow[1], tm1);
        const float f0 = exp2f(mrow[0] - mn0), f1 = exp2f(mrow[1] - mn1);
        mrow[0] = mn0; mrow[1] = mn1;
#pragma unroll
        for (int nd = 0; nd < 16; nd++) {
            oacc[nd][0] *= f0; oacc[nd][1] *= f0;
            oacc[nd][2] *= f1; oacc[nd][3] *= f1;
        }

        // ---- PV: unsplit P, exp/pack interleaved ----
        float rs0 = 0.f, rs1 = 0.f;
#pragma unroll
        for (int c = 0; c < 8; c++) {
            float e00 = exp2f(sacc[2*c][0]   - mn0);
            float e01 = exp2f(sacc[2*c][1]   - mn0);
            float e02 = exp2f(sacc[2*c][2]   - mn1);
            float e03 = exp2f(sacc[2*c][3]   - mn1);
            float e10 = exp2f(sacc[2*c+1][0] - mn0);
            float e11 = exp2f(sacc[2*c+1][1] - mn0);
            float e12 = exp2f(sacc[2*c+1][2] - mn1);
            float e13 = exp2f(sacc[2*c+1][3] - mn1);
            rs0 += (e00 + e01) + (e10 + e11);
            rs1 += (e02 + e03) + (e12 + e13);
            uint32_t ph4[4];
            ph4[0] = pack2(e00, e01);
            ph4[1] = pack2(e02, e03);
            ph4[2] = pack2(e10, e11);
            ph4[3] = pack2(e12, e13);
#pragma unroll
            for (int j = 0; j < 8; j++) {
                uint32_t boff = (uint32_t)((c*16 + (((lane >> 3) & 1) << 3) + (lane & 7)) * FSTR
                                           + j*16 + ((lane >> 4) << 3)) * 2;
                uint32_t vh4[4];
                ldm4t(vh4, sVh + boff);
                mma16(oacc[2*j],   ph4, vh4);
                mma16(oacc[2*j+1], ph4, vh4 + 2);
            }
        }
        rs0 += __shfl_xor_sync(0xffffffffu, rs0, 1);
        rs0 += __shfl_xor_sync(0xffffffffu, rs0, 2);
        rs1 += __shfl_xor_sync(0xffffffffu, rs1, 1);
        rs1 += __shfl_xor_sync(0xffffffffu, rs1, 2);
        lrow[0] = lrow[0] * f0 + rs0;
        lrow[1] = lrow[1] * f1 + rs1;
    }

    // ---- epilogue: O /= l, single fp16 write ----
    const float i0 = 1.f / lrow[0], i1 = 1.f / lrow[1];
    const long long orow0 = (long long)(b * SS + q0 + warp*16 + lr) * HIDDEN + h * DD;
    const long long orow1 = orow0 + 8LL * HIDDEN;
#pragma unroll
    for (int nd = 0; nd < 16; nd++) {
        const int col = nd * 8 + 2 * lc;
        *(uint32_t*)(O_ + orow0 + col) = pack2(oacc[nd][0] * i0, oacc[nd][1] * i0);
        *(uint32_t*)(O_ + orow1 + col) = pack2(oacc[nd][2] * i1, oacc[nd][3] * i1);
    }
}

// ---------------------------------------------------------------------------

extern "C" void kernel_launch(void* const* d_in, const int* in_sizes, int n_in,
                              void* d_out, int out_size) {
    const float* x  = (const float*)d_in[0];
    const float* qw = (const float*)d_in[1];
    const float* kw = (const float*)d_in[2];
    const float* vw = (const float*)d_in[3];
    const float* ow = (const float*)d_in[4];
    float* out = (float*)d_out;

    __half *xp,*w,*owp,*q,*kv,*at;
    cudaGetSymbolAddress((void**)&xp,  g_x);
    cudaGetSymbolAddress((void**)&w,   g_w);   cudaGetSymbolAddress((void**)&owp, g_ow);
    cudaGetSymbolAddress((void**)&q,   g_q);
    cudaGetSymbolAddress((void**)&kv,  g_kv);  cudaGetSymbolAddress((void**)&at,  g_at);

    cudaFuncSetAttribute((const void*)gemm_f16<0>,
                         cudaFuncAttributeMaxDynamicSharedMemorySize, SMEMG);
    cudaFuncSetAttribute((const void*)gemm_f16<1>,
                         cudaFuncAttributeMaxDynamicSharedMemorySize, SMEMG);
    cudaFuncSetAttribute((const void*)flash_attn,
                         cudaFuncAttributeMaxDynamicSharedMemorySize, FSMEM);

    // 0) fused prep
    prep<<<PREP_X_BLKS + PREP_W_BLKS + PREP_OW_BLKS, 256>>>(
        x, qw, kw, vw, ow, xp, w, owp);

    // 1) fused QKV projection (single fp16 everywhere)
    gemm_f16<0><<<dim3(NQKV/BN, (BB*SS)/BM), 256, SMEMG>>>(
        xp, w, q, kv, nullptr);

    // 2) fused attention (Q single, P unsplit)
    flash_attn<<<dim3(SS/TQ, BB*HEADS), 256, FSMEM>>>(q, kv, at);

    // 3) out = attn @ Ow^T
    gemm_f16<1><<<dim3(HIDDEN/BN, (BB*SS)/BM), 256, SMEMG>>>(
        at, owp, nullptr, nullptr, out);
}